// round 9
// baseline (speedup 1.0000x reference)
#include <cuda_runtime.h>
#include <cuda_fp16.h>
#include <math.h>
#include <stdint.h>

#define NN 100000
#define EE 400000
#define HC 200      // HEADS*OUT_CH
#define CC 100      // OUT_CH
#define TD 100      // TIME_DIM
#define FW 1200     // fused width: q(200)|k(200)|v(200)|skip(200)|u(400)
#define TBM 128
#define TBN 64
#define BST 72
#define AST 108
#define GEMM_SMEM ((TBM * AST + 104 * BST) * 4)

// ---------------- scratch (device globals; allocation-free) ----------------
__device__ __align__(16) float  d_fused[(size_t)NN * FW];   // 480 MB
__device__ __align__(16) float  d_aggea[(size_t)NN * 400];  // 160 MB
__device__ __align__(16) __half d_kv16[(size_t)NN * 400];   // 80 MB  k(200)|v(200)
__device__ __align__(16) float  d_W[100 * FW];
__device__ __align__(16) float  d_bias[FW];
__device__ __align__(16) int4   d_edge[EE];                 // {src, eid, rel_bits, 0}
__device__ int d_cnt[NN];
__device__ int d_rowptr[NN + 1];
__device__ int d_cursor[NN];
__device__ int d_tmpscan[NN];
__device__ int d_bsum[256];
__device__ int d_boff[256];

// ---------------- accurate cos, fp32-only Cody-Waite reduction ----------------
__device__ __forceinline__ float cos_acc(float y) {
    float k = rintf(y * 0.15915494309189535f);
    float r = fmaf(k, -6.2831854820251465f, y);
    r = fmaf(k, 1.7484556000744e-7f, r);
    return cosf(r);
}

__device__ __forceinline__ uint32_t f2tf32(float f) {
    uint32_t u;
    asm("cvt.rna.tf32.f32 %0, %1;" : "=r"(u) : "f"(f));
    return u;
}

__device__ __forceinline__ void mma_tf32(float c[4],
                                         uint32_t a0, uint32_t a1, uint32_t a2, uint32_t a3,
                                         uint32_t b0, uint32_t b1) {
    asm volatile(
        "mma.sync.aligned.m16n8k8.row.col.f32.tf32.tf32.f32 "
        "{%0,%1,%2,%3}, {%4,%5,%6,%7}, {%8,%9}, {%0,%1,%2,%3};"
        : "+f"(c[0]), "+f"(c[1]), "+f"(c[2]), "+f"(c[3])
        : "r"(a0), "r"(a1), "r"(a2), "r"(a3), "r"(b0), "r"(b1));
}

// ---------------- weight packing ----------------
__global__ void pack_w_k(const float* __restrict__ Wq, const float* __restrict__ Wk,
                         const float* __restrict__ Wv, const float* __restrict__ Ws,
                         const float* __restrict__ We) {
    int idx = blockIdx.x * blockDim.x + threadIdx.x;
    if (idx >= 100 * FW) return;
    int k = idx / FW;
    int c = idx % FW;
    float val;
    if (c < 200)       val = Wq[k * HC + c];
    else if (c < 400)  val = Wk[k * HC + (c - 200)];
    else if (c < 600)  val = Wv[k * HC + (c - 400)];
    else if (c < 800)  val = Ws[k * HC + (c - 600)];
    else {
        int c2 = c - 800;
        int h = c2 / 200, i = c2 % 200;
        float s = 0.f;
        for (int cc = 0; cc < CC; cc++)
            s += Wq[k * HC + h * CC + cc] * We[i * HC + h * CC + cc];
        val = s;
    }
    d_W[idx] = val;
}

__global__ void pack_b_k(const float* __restrict__ bq, const float* __restrict__ bk,
                         const float* __restrict__ bv, const float* __restrict__ bs,
                         const float* __restrict__ We) {
    int c = blockIdx.x * blockDim.x + threadIdx.x;
    if (c >= FW) return;
    float val;
    if (c < 200)       val = bq[c];
    else if (c < 400)  val = bk[c - 200];
    else if (c < 600)  val = bv[c - 400];
    else if (c < 800)  val = bs[c - 600];
    else {
        int c2 = c - 800;
        int h = c2 / 200, i = c2 % 200;
        float s = 0.f;
        for (int cc = 0; cc < CC; cc++)
            s += bq[h * CC + cc] * We[i * HC + h * CC + cc];
        val = s;
    }
    d_bias[c] = val;
}

// ---------------- tf32 tensor-core GEMM (K=100, A resident) ----------------
// Cols [200,600) are emitted ONLY as fp16 into d_kv16 (fp32 store skipped).
__global__ void __launch_bounds__(256) gemm_tf32_k(
    const float* __restrict__ A, int lda,
    const float* __restrict__ B, int ldb,
    float* __restrict__ C, int ldc,
    int M, int Ncol,
    const float* __restrict__ bias,
    __half* __restrict__ kv16)
{
    extern __shared__ uint32_t sm[];
    uint32_t* As = sm;               // [TBM][AST]
    uint32_t* Bs = sm + TBM * AST;   // [104][BST]

    const int t    = threadIdx.x;
    const int lane = t & 31;
    const int wid  = t >> 5;
    const int m0   = blockIdx.x * TBM;
    const int wm   = (wid >> 1) * 32;
    const int wn   = (wid & 1) * 32;

    for (int i = t; i < TBM * 8; i += 256) {
        int r = i >> 3;
        As[r * AST + 100 + (i & 7)] = 0;
    }
    for (int i = t; i < 4 * BST; i += 256)
        Bs[(100 + i / BST) * BST + (i % BST)] = 0;

    for (int i = t; i < TBM * 100; i += 256) {
        int r = i / 100, c = i - r * 100;
        int gr = m0 + r;
        float v = (gr < M) ? A[(size_t)gr * lda + c] : 0.f;
        As[r * AST + c] = f2tf32(v);
    }

    const int nch = (Ncol + TBN - 1) / TBN;
    float pb[25];
#pragma unroll
    for (int j = 0; j < 25; j++) {
        int i = t + j * 256;
        int k = i >> 6, n = i & 63;
        pb[j] = (n < Ncol) ? B[(size_t)k * ldb + n] : 0.f;
    }
    __syncthreads();

    const int arow = wm + (lane >> 2);
    const int acol = lane & 3;
    const int brow = lane & 3;
    const int bcol = wn + (lane >> 2);

    for (int cidx = 0; cidx < nch; cidx++) {
#pragma unroll
        for (int j = 0; j < 25; j++) {
            int i = t + j * 256;
            int k = i >> 6, n = i & 63;
            Bs[k * BST + n] = f2tf32(pb[j]);
        }
        __syncthreads();

        const int n0 = cidx * TBN;
        if (cidx + 1 < nch) {
            int n0n = n0 + TBN;
#pragma unroll
            for (int j = 0; j < 25; j++) {
                int i = t + j * 256;
                int k = i >> 6, n = i & 63;
                int gc = n0n + n;
                pb[j] = (gc < Ncol) ? B[(size_t)k * ldb + gc] : 0.f;
            }
        }

        float acc[2][4][4];
#pragma unroll
        for (int mt = 0; mt < 2; mt++)
#pragma unroll
            for (int nt = 0; nt < 4; nt++)
#pragma unroll
                for (int r = 0; r < 4; r++) acc[mt][nt][r] = 0.f;

#pragma unroll
        for (int ks = 0; ks < 13; ks++) {
            const int k0 = ks * 8;
            uint32_t a[2][4];
#pragma unroll
            for (int mt = 0; mt < 2; mt++) {
                int r = arow + mt * 16;
                a[mt][0] = As[r * AST + k0 + acol];
                a[mt][1] = As[(r + 8) * AST + k0 + acol];
                a[mt][2] = As[r * AST + k0 + acol + 4];
                a[mt][3] = As[(r + 8) * AST + k0 + acol + 4];
            }
            uint32_t b[4][2];
#pragma unroll
            for (int nt = 0; nt < 4; nt++) {
                b[nt][0] = Bs[(k0 + brow) * BST + bcol + nt * 8];
                b[nt][1] = Bs[(k0 + brow + 4) * BST + bcol + nt * 8];
            }
#pragma unroll
            for (int mt = 0; mt < 2; mt++)
#pragma unroll
                for (int nt = 0; nt < 4; nt++)
                    mma_tf32(acc[mt][nt], a[mt][0], a[mt][1], a[mt][2], a[mt][3],
                             b[nt][0], b[nt][1]);
        }

#pragma unroll
        for (int mt = 0; mt < 2; mt++) {
            int rbase = m0 + wm + mt * 16 + (lane >> 2);
#pragma unroll
            for (int half = 0; half < 2; half++) {
                int r = rbase + half * 8;
                if (r < M) {
#pragma unroll
                    for (int nt = 0; nt < 4; nt++) {
                        int col = n0 + wn + nt * 8 + (lane & 3) * 2;
                        if (col < Ncol) {
                            float v0 = acc[mt][nt][half * 2 + 0];
                            float v1 = acc[mt][nt][half * 2 + 1];
                            if (bias) { v0 += bias[col]; v1 += bias[col + 1]; }
                            bool iskv = kv16 && col >= 200 && col < 600;
                            if (iskv) {
                                *(__half2*)(kv16 + (size_t)r * 400 + (col - 200)) =
                                    __floats2half2_rn(v0, v1);
                            } else {
                                *(float2*)(C + (size_t)r * ldc + col) =
                                    make_float2(v0, v1);
                            }
                        }
                    }
                }
            }
        }
        __syncthreads();
    }
}

// ---------------- finals: C += A[:,0:100]@B0 + A[:,100:200]@B1, Ncol=100 ----
__global__ void __launch_bounds__(256) gemm_fin_k(
    const float* __restrict__ A,
    const float* __restrict__ B,
    float* __restrict__ C)
{
    extern __shared__ uint32_t sm[];
    uint32_t* As = sm;               // [TBM][AST]
    uint32_t* Bs = sm + TBM * AST;   // [104][BST]

    const int t    = threadIdx.x;
    const int lane = t & 31;
    const int wid  = t >> 5;
    const int m0   = blockIdx.x * TBM;
    const int wm   = (wid >> 1) * 32;
    const int wn   = (wid & 1) * 32;

    for (int i = t; i < TBM * 8; i += 256) {
        int r = i >> 3;
        As[r * AST + 100 + (i & 7)] = 0;
    }
    for (int i = t; i < 4 * BST; i += 256)
        Bs[(100 + i / BST) * BST + (i % BST)] = 0;

    const int arow = wm + (lane >> 2);
    const int acol = lane & 3;
    const int brow = lane & 3;
    const int bcol = wn + (lane >> 2);

    for (int cidx = 0; cidx < 2; cidx++) {
        const int n0 = cidx * TBN;

        float acc[2][4][4];
#pragma unroll
        for (int mt = 0; mt < 2; mt++)
#pragma unroll
            for (int nt = 0; nt < 4; nt++)
#pragma unroll
                for (int r = 0; r < 4; r++) acc[mt][nt][r] = 0.f;

        for (int kh = 0; kh < 2; kh++) {
            __syncthreads();
            const float* Ap = A + kh * 100;
            const float* Bp = B + (size_t)(kh * 100) * HC;
            for (int i = t; i < TBM * 100; i += 256) {
                int r = i / 100, c = i - r * 100;
                int gr = m0 + r;
                float v = (gr < NN) ? Ap[(size_t)gr * 400 + c] : 0.f;
                As[r * AST + c] = f2tf32(v);
            }
            for (int i = t; i < 100 * TBN; i += 256) {
                int k = i >> 6, n = i & 63;
                int gc = n0 + n;
                Bs[k * BST + n] = f2tf32((gc < CC) ? Bp[(size_t)k * HC + gc] : 0.f);
            }
            __syncthreads();

#pragma unroll
            for (int ks = 0; ks < 13; ks++) {
                const int k0 = ks * 8;
                uint32_t a[2][4];
#pragma unroll
                for (int mt = 0; mt < 2; mt++) {
                    int r = arow + mt * 16;
                    a[mt][0] = As[r * AST + k0 + acol];
                    a[mt][1] = As[(r + 8) * AST + k0 + acol];
                    a[mt][2] = As[r * AST + k0 + acol + 4];
                    a[mt][3] = As[(r + 8) * AST + k0 + acol + 4];
                }
                uint32_t b[4][2];
#pragma unroll
                for (int nt = 0; nt < 4; nt++) {
                    b[nt][0] = Bs[(k0 + brow) * BST + bcol + nt * 8];
                    b[nt][1] = Bs[(k0 + brow + 4) * BST + bcol + nt * 8];
                }
#pragma unroll
                for (int mt = 0; mt < 2; mt++)
#pragma unroll
                    for (int nt = 0; nt < 4; nt++)
                        mma_tf32(acc[mt][nt], a[mt][0], a[mt][1], a[mt][2], a[mt][3],
                                 b[nt][0], b[nt][1]);
            }
        }

#pragma unroll
        for (int mt = 0; mt < 2; mt++) {
            int rbase = m0 + wm + mt * 16 + (lane >> 2);
#pragma unroll
            for (int half = 0; half < 2; half++) {
                int r = rbase + half * 8;
                if (r < NN) {
#pragma unroll
                    for (int nt = 0; nt < 4; nt++) {
                        int col = n0 + wn + nt * 8 + (lane & 3) * 2;
                        if (col < CC) {
                            float* cp = C + (size_t)r * HC + col;
                            float v0 = acc[mt][nt][half * 2 + 0] + cp[0];
                            float v1 = acc[mt][nt][half * 2 + 1] + cp[1];
                            *(float2*)cp = make_float2(v0, v1);
                        }
                    }
                }
            }
        }
    }
}

// ---------------- CSR build ----------------
__global__ void zero_cnt_k() {
    int i = blockIdx.x * blockDim.x + threadIdx.x;
    if (i < NN) d_cnt[i] = 0;
}
__global__ void hist_k(const int* __restrict__ ei) {
    int e = blockIdx.x * blockDim.x + threadIdx.x;
    if (e < EE) atomicAdd(&d_cnt[ei[EE + e]], 1);
}
__global__ void scan1_k() {
    __shared__ int ws[32];
    int i = blockIdx.x * 1024 + threadIdx.x;
    int v = (i < NN) ? d_cnt[i] : 0;
    int lane = threadIdx.x & 31, wid = threadIdx.x >> 5;
    int s = v;
#pragma unroll
    for (int d = 1; d < 32; d <<= 1) {
        int tv = __shfl_up_sync(0xffffffffu, s, d);
        if (lane >= d) s += tv;
    }
    if (lane == 31) ws[wid] = s;
    __syncthreads();
    if (wid == 0) {
        int t2 = ws[lane];
#pragma unroll
        for (int d = 1; d < 32; d <<= 1) {
            int tv = __shfl_up_sync(0xffffffffu, t2, d);
            if (lane >= d) t2 += tv;
        }
        ws[lane] = t2;
    }
    __syncthreads();
    int add = (wid > 0) ? ws[wid - 1] : 0;
    s += add;
    if (i < NN) d_tmpscan[i] = s;
    if (threadIdx.x == 1023) d_bsum[blockIdx.x] = s;
}
__global__ void scan2_k(int nb) {
    if (threadIdx.x == 0 && blockIdx.x == 0) {
        int acc = 0;
        for (int b = 0; b < nb; b++) { int t = d_bsum[b]; d_boff[b] = acc; acc += t; }
    }
}
__global__ void scan3_k() {
    int i = blockIdx.x * blockDim.x + threadIdx.x;
    if (i < NN) {
        int rp = (i == 0) ? 0 : (d_tmpscan[i - 1] + d_boff[(i - 1) >> 10]);
        d_rowptr[i] = rp;
        d_cursor[i] = rp;
        if (i == NN - 1) d_rowptr[NN] = d_tmpscan[i] + d_boff[i >> 10];
    }
}
// scatter + precompute per-edge record {src, eid, rel}
__global__ void scatter_k(const int* __restrict__ ei,
                          const float* __restrict__ tarr,
                          const float* __restrict__ lastup) {
    int e = blockIdx.x * blockDim.x + threadIdx.x;
    if (e < EE) {
        int src = ei[e];
        int dst = ei[EE + e];
        float rel = fabsf(__ldg(lastup + src) - __ldg(tarr + e));
        int p = atomicAdd(&d_cursor[dst], 1);
        d_edge[p] = make_int4(src, e, __float_as_int(rel), 0);
    }
}

// ---------------- fused single-pass online-softmax attention ----------------
// warp per node; 2-stage pipeline; fp16 k/v gathers; 1-level dependency.
__global__ void __launch_bounds__(128) attn_k(
    const float* __restrict__ msg,
    const float* __restrict__ w_time,
    const float* __restrict__ b_time,
    float* __restrict__ out)
{
    __shared__ float s_wt[TD], s_bt[TD];
    for (int i = threadIdx.x; i < TD; i += 128) { s_wt[i] = w_time[i]; s_bt[i] = b_time[i]; }
    __syncthreads();

    int warp = (blockIdx.x * 128 + threadIdx.x) >> 5;
    int lane = threadIdx.x & 31;
    if (warp >= NN) return;
    const int n = warp;
    const int base = d_rowptr[n];
    const int deg  = d_rowptr[n + 1] - base;

    const float2* frow2 = (const float2*)(d_fused + (size_t)n * FW);

    bool jok[4], jh1[4];
    int  ji[4];
#pragma unroll
    for (int s = 0; s < 4; s++) {
        int j2 = s * 64 + lane * 2;
        jok[s] = j2 < 200; jh1[s] = j2 >= 100; ji[s] = s * 32 + lane;
    }
    bool iok[2]; int ii[2]; int i2v[2];
#pragma unroll
    for (int r = 0; r < 2; r++) {
        int i2 = r * 64 + lane * 2;
        iok[r] = i2 < 100; ii[r] = r * 32 + lane; i2v[r] = i2;
    }

    const float2 zz = make_float2(0.f, 0.f);
    float2 qv[4];
#pragma unroll
    for (int s = 0; s < 4; s++) qv[s] = jok[s] ? frow2[ji[s]] : zz;
    float2 u0t[2], u0m[2], u1t[2], u1m[2];
#pragma unroll
    for (int r = 0; r < 2; r++) {
        u0t[r] = iok[r] ? frow2[400 + ii[r]] : zz;
        u0m[r] = iok[r] ? frow2[450 + ii[r]] : zz;
        u1t[r] = iok[r] ? frow2[500 + ii[r]] : zz;
        u1m[r] = iok[r] ? frow2[550 + ii[r]] : zz;
    }

    float m0 = -INFINITY, m1 = -INFINITY, den0 = 0.f, den1 = 0.f;
    float2 vac[4];
#pragma unroll
    for (int s = 0; s < 4; s++) vac[s] = zz;
    float2 e0t[2], e0m[2], e1t[2], e1m[2];
#pragma unroll
    for (int r = 0; r < 2; r++) { e0t[r] = zz; e0m[r] = zz; e1t[r] = zz; e1m[r] = zz; }

    float relA = 0.f, relB = 0.f;
    float2 kvA[4], vvA[4], mgA[2], kvB[4], vvB[4], mgB[2];

    auto load_edge = [&](int idx, float& rel, float2* kv, float2* vv, float2* mg) {
        int4 rec = d_edge[base + idx];          // {src, eid, rel_bits, 0}
        int src = rec.x, eid = rec.y;
        rel = __int_as_float(rec.z);
        const __half2* s2 = (const __half2*)(d_kv16 + (size_t)src * 400);
#pragma unroll
        for (int s = 0; s < 4; s++) {
            kv[s] = jok[s] ? __half22float2(s2[ji[s]])       : zz;
            vv[s] = jok[s] ? __half22float2(s2[100 + ji[s]]) : zz;
        }
        const float2* m2 = (const float2*)(msg + (size_t)eid * 100);
#pragma unroll
        for (int r = 0; r < 2; r++) mg[r] = iok[r] ? m2[ii[r]] : zz;
    };

    auto process = [&](float rel, const float2* kv, const float2* vv, const float2* mg) {
        float2 te[2];
        float a0 = 0.f, a1 = 0.f;
#pragma unroll
        for (int r = 0; r < 2; r++) {
            if (iok[r]) {
                int i2 = i2v[r];
                float y0 = __fadd_rn(__fmul_rn(rel, s_wt[i2]),     s_bt[i2]);
                float y1 = __fadd_rn(__fmul_rn(rel, s_wt[i2 + 1]), s_bt[i2 + 1]);
                te[r].x = cos_acc(y0);
                te[r].y = cos_acc(y1);
            } else te[r] = zz;
            a0 += te[r].x * u0t[r].x + te[r].y * u0t[r].y
                + mg[r].x * u0m[r].x + mg[r].y * u0m[r].y;
            a1 += te[r].x * u1t[r].x + te[r].y * u1t[r].y
                + mg[r].x * u1m[r].x + mg[r].y * u1m[r].y;
        }
#pragma unroll
        for (int s = 0; s < 4; s++) {
            float dp = qv[s].x * kv[s].x + qv[s].y * kv[s].y;
            if (jh1[s]) a1 += dp; else a0 += dp;
        }
#pragma unroll
        for (int o = 16; o > 0; o >>= 1) {
            a0 += __shfl_xor_sync(0xffffffffu, a0, o);
            a1 += __shfl_xor_sync(0xffffffffu, a1, o);
        }
        a0 *= 0.1f; a1 *= 0.1f;

        float nm0 = fmaxf(m0, a0), nm1 = fmaxf(m1, a1);
        float f0 = __expf(m0 - nm0), f1 = __expf(m1 - nm1);
        float w0 = __expf(a0 - nm0), w1 = __expf(a1 - nm1);
        m0 = nm0; m1 = nm1;
        den0 = den0 * f0 + w0;
        den1 = den1 * f1 + w1;
#pragma unroll
        for (int s = 0; s < 4; s++) {
            float f = jh1[s] ? f1 : f0, w = jh1[s] ? w1 : w0;
            vac[s].x = vac[s].x * f + w * vv[s].x;
            vac[s].y = vac[s].y * f + w * vv[s].y;
        }
#pragma unroll
        for (int r = 0; r < 2; r++) {
            e0t[r].x = e0t[r].x * f0 + w0 * te[r].x;  e0t[r].y = e0t[r].y * f0 + w0 * te[r].y;
            e0m[r].x = e0m[r].x * f0 + w0 * mg[r].x;  e0m[r].y = e0m[r].y * f0 + w0 * mg[r].y;
            e1t[r].x = e1t[r].x * f1 + w1 * te[r].x;  e1t[r].y = e1t[r].y * f1 + w1 * te[r].y;
            e1m[r].x = e1m[r].x * f1 + w1 * mg[r].x;  e1m[r].y = e1m[r].y * f1 + w1 * mg[r].y;
        }
    };

    if (deg > 0) load_edge(0, relA, kvA, vvA, mgA);
    int d = 0;
    while (d < deg) {
        if (d + 1 < deg) load_edge(d + 1, relB, kvB, vvB, mgB);
        process(relA, kvA, vvA, mgA);
        if (++d >= deg) break;
        if (d + 1 < deg) load_edge(d + 1, relA, kvA, vvA, mgA);
        process(relB, kvB, vvB, mgB);
        ++d;
    }

    float inv0 = 1.f / (den0 + 1e-16f), inv1 = 1.f / (den1 + 1e-16f);
    float2* out2 = (float2*)(out + (size_t)n * HC);
#pragma unroll
    for (int s = 0; s < 4; s++) {
        if (jok[s]) {
            float inv = jh1[s] ? inv1 : inv0;
            float2 sk = frow2[300 + ji[s]];
            out2[ji[s]] = make_float2(sk.x + vac[s].x * inv, sk.y + vac[s].y * inv);
        }
    }
    float2* ae2 = (float2*)(d_aggea + (size_t)n * 400);
#pragma unroll
    for (int r = 0; r < 2; r++) {
        if (iok[r]) {
            ae2[ii[r]]       = make_float2(e0t[r].x * inv0, e0t[r].y * inv0);
            ae2[50 + ii[r]]  = make_float2(e0m[r].x * inv0, e0m[r].y * inv0);
            ae2[100 + ii[r]] = make_float2(e1t[r].x * inv1, e1t[r].y * inv1);
            ae2[150 + ii[r]] = make_float2(e1m[r].x * inv1, e1m[r].y * inv1);
        }
    }
}

// ---------------- launch ----------------
extern "C" void kernel_launch(void* const* d_in, const int* in_sizes, int n_in,
                              void* d_out, int out_size)
{
    const float* x       = (const float*)d_in[0];
    const float* last_up = (const float*)d_in[1];
    const int*   ei      = (const int*)  d_in[2];
    const float* tarr    = (const float*)d_in[3];
    const float* msg     = (const float*)d_in[4];
    const float* w_time  = (const float*)d_in[5];
    const float* b_time  = (const float*)d_in[6];
    const float* Wq      = (const float*)d_in[7];
    const float* bq      = (const float*)d_in[8];
    const float* Wk      = (const float*)d_in[9];
    const float* bk      = (const float*)d_in[10];
    const float* Wv      = (const float*)d_in[11];
    const float* bv      = (const float*)d_in[12];
    const float* We      = (const float*)d_in[13];
    const float* Ws      = (const float*)d_in[14];
    const float* bs      = (const float*)d_in[15];
    float* out = (float*)d_out;

    float *fused_p, *ae_p, *w_p, *b_p;
    __half* kv16_p;
    cudaGetSymbolAddress((void**)&fused_p, d_fused);
    cudaGetSymbolAddress((void**)&ae_p,    d_aggea);
    cudaGetSymbolAddress((void**)&w_p,     d_W);
    cudaGetSymbolAddress((void**)&b_p,     d_bias);
    cudaGetSymbolAddress((void**)&kv16_p,  d_kv16);

    cudaFuncSetAttribute(gemm_tf32_k,
                         cudaFuncAttributeMaxDynamicSharedMemorySize, GEMM_SMEM);
    cudaFuncSetAttribute(gemm_fin_k,
                         cudaFuncAttributeMaxDynamicSharedMemorySize, GEMM_SMEM);

    pack_w_k<<<(100 * FW + 255) / 256, 256>>>(Wq, Wk, Wv, Ws, We);   // 0
    pack_b_k<<<(FW + 255) / 256, 256>>>(bq, bk, bv, bs, We);         // 1
    zero_cnt_k<<<(NN + 255) / 256, 256>>>();                         // 2

    const int gx = (NN + TBM - 1) / TBM;   // 782
    // 3 (profiled slot): mega GEMM; k|v emitted fp16-only
    gemm_tf32_k<<<gx, 256, GEMM_SMEM>>>(x, 100, w_p, FW, fused_p, FW,
                                        NN, FW, b_p, kv16_p);

    // CSR by dst (+ per-edge record precompute in scatter)
    hist_k<<<(EE + 255) / 256, 256>>>(ei);
    int nb = (NN + 1023) / 1024;
    scan1_k<<<nb, 1024>>>();
    scan2_k<<<1, 32>>>(nb);
    scan3_k<<<(NN + 255) / 256, 256>>>();
    scatter_k<<<(EE + 255) / 256, 256>>>(ei, tarr, last_up);

    // single-pass attention (warp per node)
    attn_k<<<(NN + 3) / 4, 128>>>(msg, w_time, b_time, out);

    // finals: one fused K=200 accumulate per head
    for (int h = 0; h < 2; h++) {
        gemm_fin_k<<<gx, 256, GEMM_SMEM>>>(ae_p + h * 200, We + h * 100,
                                           out + h * 100);
    }
}

// round 10
// speedup vs baseline: 1.0316x; 1.0316x over previous
#include <cuda_runtime.h>
#include <math.h>
#include <stdint.h>

#define NN 100000
#define EE 400000
#define HC 200      // HEADS*OUT_CH
#define CC 100      // OUT_CH
#define TD 100      // TIME_DIM
#define FW 1200     // fused width: q(200)|k(200)|v(200)|skip(200)|u(400)
#define TBM 128
#define TBN 64
#define BST 72
#define AST 108
#define GEMM_SMEM ((TBM * AST + 104 * BST) * 4)

// ---------------- scratch (device globals; allocation-free) ----------------
__device__ __align__(16) float d_fused[(size_t)NN * FW];   // 480 MB
__device__ __align__(16) float d_aggea[(size_t)NN * 400];  // 160 MB
__device__ __align__(16) float d_W[100 * FW];
__device__ __align__(16) float d_bias[FW];
__device__ __align__(16) int4  d_edge[EE];                 // {src, eid, rel_bits, 0}
__device__ int d_cnt[NN];
__device__ int d_rowptr[NN + 1];
__device__ int d_cursor[NN];
__device__ int d_tmpscan[NN];
__device__ int d_bsum[256];
__device__ int d_boff[256];

// ---------------- accurate cos, fp32-only Cody-Waite reduction ----------------
__device__ __forceinline__ float cos_acc(float y) {
    float k = rintf(y * 0.15915494309189535f);
    float r = fmaf(k, -6.2831854820251465f, y);
    r = fmaf(k, 1.7484556000744e-7f, r);
    return cosf(r);
}

__device__ __forceinline__ uint32_t f2tf32(float f) {
    uint32_t u;
    asm("cvt.rna.tf32.f32 %0, %1;" : "=r"(u) : "f"(f));
    return u;
}

__device__ __forceinline__ void mma_tf32(float c[4],
                                         uint32_t a0, uint32_t a1, uint32_t a2, uint32_t a3,
                                         uint32_t b0, uint32_t b1) {
    asm volatile(
        "mma.sync.aligned.m16n8k8.row.col.f32.tf32.tf32.f32 "
        "{%0,%1,%2,%3}, {%4,%5,%6,%7}, {%8,%9}, {%0,%1,%2,%3};"
        : "+f"(c[0]), "+f"(c[1]), "+f"(c[2]), "+f"(c[3])
        : "r"(a0), "r"(a1), "r"(a2), "r"(a3), "r"(b0), "r"(b1));
}

// ---------------- weight packing ----------------
__global__ void pack_w_k(const float* __restrict__ Wq, const float* __restrict__ Wk,
                         const float* __restrict__ Wv, const float* __restrict__ Ws,
                         const float* __restrict__ We) {
    int idx = blockIdx.x * blockDim.x + threadIdx.x;
    if (idx >= 100 * FW) return;
    int k = idx / FW;
    int c = idx % FW;
    float val;
    if (c < 200)       val = Wq[k * HC + c];
    else if (c < 400)  val = Wk[k * HC + (c - 200)];
    else if (c < 600)  val = Wv[k * HC + (c - 400)];
    else if (c < 800)  val = Ws[k * HC + (c - 600)];
    else {
        int c2 = c - 800;
        int h = c2 / 200, i = c2 % 200;
        float s = 0.f;
        for (int cc = 0; cc < CC; cc++)
            s += Wq[k * HC + h * CC + cc] * We[i * HC + h * CC + cc];
        val = s;
    }
    d_W[idx] = val;
}

__global__ void pack_b_k(const float* __restrict__ bq, const float* __restrict__ bk,
                         const float* __restrict__ bv, const float* __restrict__ bs,
                         const float* __restrict__ We) {
    int c = blockIdx.x * blockDim.x + threadIdx.x;
    if (c >= FW) return;
    float val;
    if (c < 200)       val = bq[c];
    else if (c < 400)  val = bk[c - 200];
    else if (c < 600)  val = bv[c - 400];
    else if (c < 800)  val = bs[c - 600];
    else {
        int c2 = c - 800;
        int h = c2 / 200, i = c2 % 200;
        float s = 0.f;
        for (int cc = 0; cc < CC; cc++)
            s += bq[h * CC + cc] * We[i * HC + h * CC + cc];
        val = s;
    }
    d_bias[c] = val;
}

// ---------------- tf32 tensor-core GEMM (K=100, A resident) ----------------
__global__ void __launch_bounds__(256) gemm_tf32_k(
    const float* __restrict__ A, int lda,
    const float* __restrict__ B, int ldb,
    float* __restrict__ C, int ldc,
    int M, int Ncol,
    const float* __restrict__ bias)
{
    extern __shared__ uint32_t sm[];
    uint32_t* As = sm;               // [TBM][AST]
    uint32_t* Bs = sm + TBM * AST;   // [104][BST]

    const int t    = threadIdx.x;
    const int lane = t & 31;
    const int wid  = t >> 5;
    const int m0   = blockIdx.x * TBM;
    const int wm   = (wid >> 1) * 32;
    const int wn   = (wid & 1) * 32;

    for (int i = t; i < TBM * 8; i += 256) {
        int r = i >> 3;
        As[r * AST + 100 + (i & 7)] = 0;
    }
    for (int i = t; i < 4 * BST; i += 256)
        Bs[(100 + i / BST) * BST + (i % BST)] = 0;

    for (int i = t; i < TBM * 100; i += 256) {
        int r = i / 100, c = i - r * 100;
        int gr = m0 + r;
        float v = (gr < M) ? A[(size_t)gr * lda + c] : 0.f;
        As[r * AST + c] = f2tf32(v);
    }

    const int nch = (Ncol + TBN - 1) / TBN;
    float pb[25];
#pragma unroll
    for (int j = 0; j < 25; j++) {
        int i = t + j * 256;
        int k = i >> 6, n = i & 63;
        pb[j] = (n < Ncol) ? B[(size_t)k * ldb + n] : 0.f;
    }
    __syncthreads();

    const int arow = wm + (lane >> 2);
    const int acol = lane & 3;
    const int brow = lane & 3;
    const int bcol = wn + (lane >> 2);

    for (int cidx = 0; cidx < nch; cidx++) {
#pragma unroll
        for (int j = 0; j < 25; j++) {
            int i = t + j * 256;
            int k = i >> 6, n = i & 63;
            Bs[k * BST + n] = f2tf32(pb[j]);
        }
        __syncthreads();

        const int n0 = cidx * TBN;
        if (cidx + 1 < nch) {
            int n0n = n0 + TBN;
#pragma unroll
            for (int j = 0; j < 25; j++) {
                int i = t + j * 256;
                int k = i >> 6, n = i & 63;
                int gc = n0n + n;
                pb[j] = (gc < Ncol) ? B[(size_t)k * ldb + gc] : 0.f;
            }
        }

        float acc[2][4][4];
#pragma unroll
        for (int mt = 0; mt < 2; mt++)
#pragma unroll
            for (int nt = 0; nt < 4; nt++)
#pragma unroll
                for (int r = 0; r < 4; r++) acc[mt][nt][r] = 0.f;

#pragma unroll
        for (int ks = 0; ks < 13; ks++) {
            const int k0 = ks * 8;
            uint32_t a[2][4];
#pragma unroll
            for (int mt = 0; mt < 2; mt++) {
                int r = arow + mt * 16;
                a[mt][0] = As[r * AST + k0 + acol];
                a[mt][1] = As[(r + 8) * AST + k0 + acol];
                a[mt][2] = As[r * AST + k0 + acol + 4];
                a[mt][3] = As[(r + 8) * AST + k0 + acol + 4];
            }
            uint32_t b[4][2];
#pragma unroll
            for (int nt = 0; nt < 4; nt++) {
                b[nt][0] = Bs[(k0 + brow) * BST + bcol + nt * 8];
                b[nt][1] = Bs[(k0 + brow + 4) * BST + bcol + nt * 8];
            }
#pragma unroll
            for (int mt = 0; mt < 2; mt++)
#pragma unroll
                for (int nt = 0; nt < 4; nt++)
                    mma_tf32(acc[mt][nt], a[mt][0], a[mt][1], a[mt][2], a[mt][3],
                             b[nt][0], b[nt][1]);
        }

#pragma unroll
        for (int mt = 0; mt < 2; mt++) {
            int rbase = m0 + wm + mt * 16 + (lane >> 2);
#pragma unroll
            for (int half = 0; half < 2; half++) {
                int r = rbase + half * 8;
                if (r < M) {
#pragma unroll
                    for (int nt = 0; nt < 4; nt++) {
                        int col = n0 + wn + nt * 8 + (lane & 3) * 2;
                        if (col < Ncol) {
                            float v0 = acc[mt][nt][half * 2 + 0];
                            float v1 = acc[mt][nt][half * 2 + 1];
                            if (bias) { v0 += bias[col]; v1 += bias[col + 1]; }
                            *(float2*)(C + (size_t)r * ldc + col) = make_float2(v0, v1);
                        }
                    }
                }
            }
        }
        __syncthreads();
    }
}

// ---------------- finals: C += A[:,0:100]@B0 + A[:,100:200]@B1, Ncol=100 ----
__global__ void __launch_bounds__(256) gemm_fin_k(
    const float* __restrict__ A,
    const float* __restrict__ B,
    float* __restrict__ C)
{
    extern __shared__ uint32_t sm[];
    uint32_t* As = sm;               // [TBM][AST]
    uint32_t* Bs = sm + TBM * AST;   // [104][BST]

    const int t    = threadIdx.x;
    const int lane = t & 31;
    const int wid  = t >> 5;
    const int m0   = blockIdx.x * TBM;
    const int wm   = (wid >> 1) * 32;
    const int wn   = (wid & 1) * 32;

    for (int i = t; i < TBM * 8; i += 256) {
        int r = i >> 3;
        As[r * AST + 100 + (i & 7)] = 0;
    }
    for (int i = t; i < 4 * BST; i += 256)
        Bs[(100 + i / BST) * BST + (i % BST)] = 0;

    const int arow = wm + (lane >> 2);
    const int acol = lane & 3;
    const int brow = lane & 3;
    const int bcol = wn + (lane >> 2);

    for (int cidx = 0; cidx < 2; cidx++) {
        const int n0 = cidx * TBN;

        float acc[2][4][4];
#pragma unroll
        for (int mt = 0; mt < 2; mt++)
#pragma unroll
            for (int nt = 0; nt < 4; nt++)
#pragma unroll
                for (int r = 0; r < 4; r++) acc[mt][nt][r] = 0.f;

        for (int kh = 0; kh < 2; kh++) {
            __syncthreads();
            const float* Ap = A + kh * 100;
            const float* Bp = B + (size_t)(kh * 100) * HC;
            for (int i = t; i < TBM * 100; i += 256) {
                int r = i / 100, c = i - r * 100;
                int gr = m0 + r;
                float v = (gr < NN) ? Ap[(size_t)gr * 400 + c] : 0.f;
                As[r * AST + c] = f2tf32(v);
            }
            for (int i = t; i < 100 * TBN; i += 256) {
                int k = i >> 6, n = i & 63;
                int gc = n0 + n;
                Bs[k * BST + n] = f2tf32((gc < CC) ? Bp[(size_t)k * HC + gc] : 0.f);
            }
            __syncthreads();

#pragma unroll
            for (int ks = 0; ks < 13; ks++) {
                const int k0 = ks * 8;
                uint32_t a[2][4];
#pragma unroll
                for (int mt = 0; mt < 2; mt++) {
                    int r = arow + mt * 16;
                    a[mt][0] = As[r * AST + k0 + acol];
                    a[mt][1] = As[(r + 8) * AST + k0 + acol];
                    a[mt][2] = As[r * AST + k0 + acol + 4];
                    a[mt][3] = As[(r + 8) * AST + k0 + acol + 4];
                }
                uint32_t b[4][2];
#pragma unroll
                for (int nt = 0; nt < 4; nt++) {
                    b[nt][0] = Bs[(k0 + brow) * BST + bcol + nt * 8];
                    b[nt][1] = Bs[(k0 + brow + 4) * BST + bcol + nt * 8];
                }
#pragma unroll
                for (int mt = 0; mt < 2; mt++)
#pragma unroll
                    for (int nt = 0; nt < 4; nt++)
                        mma_tf32(acc[mt][nt], a[mt][0], a[mt][1], a[mt][2], a[mt][3],
                                 b[nt][0], b[nt][1]);
            }
        }

#pragma unroll
        for (int mt = 0; mt < 2; mt++) {
            int rbase = m0 + wm + mt * 16 + (lane >> 2);
#pragma unroll
            for (int half = 0; half < 2; half++) {
                int r = rbase + half * 8;
                if (r < NN) {
#pragma unroll
                    for (int nt = 0; nt < 4; nt++) {
                        int col = n0 + wn + nt * 8 + (lane & 3) * 2;
                        if (col < CC) {
                            float* cp = C + (size_t)r * HC + col;
                            float v0 = acc[mt][nt][half * 2 + 0] + cp[0];
                            float v1 = acc[mt][nt][half * 2 + 1] + cp[1];
                            *(float2*)cp = make_float2(v0, v1);
                        }
                    }
                }
            }
        }
    }
}

// ---------------- CSR build ----------------
__global__ void zero_cnt_k() {
    int i = blockIdx.x * blockDim.x + threadIdx.x;
    if (i < NN) d_cnt[i] = 0;
}
__global__ void hist_k(const int* __restrict__ ei) {
    int e = blockIdx.x * blockDim.x + threadIdx.x;
    if (e < EE) atomicAdd(&d_cnt[ei[EE + e]], 1);
}
__global__ void scan1_k() {
    __shared__ int ws[32];
    int i = blockIdx.x * 1024 + threadIdx.x;
    int v = (i < NN) ? d_cnt[i] : 0;
    int lane = threadIdx.x & 31, wid = threadIdx.x >> 5;
    int s = v;
#pragma unroll
    for (int d = 1; d < 32; d <<= 1) {
        int tv = __shfl_up_sync(0xffffffffu, s, d);
        if (lane >= d) s += tv;
    }
    if (lane == 31) ws[wid] = s;
    __syncthreads();
    if (wid == 0) {
        int t2 = ws[lane];
#pragma unroll
        for (int d = 1; d < 32; d <<= 1) {
            int tv = __shfl_up_sync(0xffffffffu, t2, d);
            if (lane >= d) t2 += tv;
        }
        ws[lane] = t2;
    }
    __syncthreads();
    int add = (wid > 0) ? ws[wid - 1] : 0;
    s += add;
    if (i < NN) d_tmpscan[i] = s;
    if (threadIdx.x == 1023) d_bsum[blockIdx.x] = s;
}
// parallel exclusive scan of block sums (nb <= 128)
__global__ void scan2_k(int nb) {
    __shared__ int sh[128];
    int t = threadIdx.x;
    int v = (t < nb) ? d_bsum[t] : 0;
    sh[t] = v;
    __syncthreads();
#pragma unroll
    for (int o = 1; o < 128; o <<= 1) {
        int u = (t >= o) ? sh[t - o] : 0;
        __syncthreads();
        sh[t] += u;
        __syncthreads();
    }
    if (t < nb) d_boff[t] = sh[t] - v;   // exclusive prefix
}
__global__ void scan3_k() {
    int i = blockIdx.x * blockDim.x + threadIdx.x;
    if (i < NN) {
        int rp = (i == 0) ? 0 : (d_tmpscan[i - 1] + d_boff[(i - 1) >> 10]);
        d_rowptr[i] = rp;
        d_cursor[i] = rp;
        if (i == NN - 1) d_rowptr[NN] = d_tmpscan[i] + d_boff[i >> 10];
    }
}
// scatter + precompute per-edge record {src, eid, rel}
__global__ void scatter_k(const int* __restrict__ ei,
                          const float* __restrict__ tarr,
                          const float* __restrict__ lastup) {
    int e = blockIdx.x * blockDim.x + threadIdx.x;
    if (e < EE) {
        int src = ei[e];
        int dst = ei[EE + e];
        float rel = fabsf(__ldg(lastup + src) - __ldg(tarr + e));
        int p = atomicAdd(&d_cursor[dst], 1);
        d_edge[p] = make_int4(src, e, __float_as_int(rel), 0);
    }
}

// ---------------- fused single-pass online-softmax attention ----------------
// warp per node; 2-stage register pipeline + L2 prefetch 3 edges ahead.
__global__ void __launch_bounds__(128) attn_k(
    const float* __restrict__ msg,
    const float* __restrict__ w_time,
    const float* __restrict__ b_time,
    float* __restrict__ out)
{
    __shared__ float s_wt[TD], s_bt[TD];
    for (int i = threadIdx.x; i < TD; i += 128) { s_wt[i] = w_time[i]; s_bt[i] = b_time[i]; }
    __syncthreads();

    int warp = (blockIdx.x * 128 + threadIdx.x) >> 5;
    int lane = threadIdx.x & 31;
    if (warp >= NN) return;
    const int n = warp;
    const int base = d_rowptr[n];
    const int deg  = d_rowptr[n + 1] - base;

    const float2* frow2 = (const float2*)(d_fused + (size_t)n * FW);

    bool jok[4], jh1[4];
    int  ji[4];
#pragma unroll
    for (int s = 0; s < 4; s++) {
        int j2 = s * 64 + lane * 2;
        jok[s] = j2 < 200; jh1[s] = j2 >= 100; ji[s] = s * 32 + lane;
    }
    bool iok[2]; int ii[2]; int i2v[2];
#pragma unroll
    for (int r = 0; r < 2; r++) {
        int i2 = r * 64 + lane * 2;
        iok[r] = i2 < 100; ii[r] = r * 32 + lane; i2v[r] = i2;
    }

    const float2 zz = make_float2(0.f, 0.f);
    float2 qv[4];
#pragma unroll
    for (int s = 0; s < 4; s++) qv[s] = jok[s] ? frow2[ji[s]] : zz;
    float2 u0t[2], u0m[2], u1t[2], u1m[2];
#pragma unroll
    for (int r = 0; r < 2; r++) {
        u0t[r] = iok[r] ? frow2[400 + ii[r]] : zz;
        u0m[r] = iok[r] ? frow2[450 + ii[r]] : zz;
        u1t[r] = iok[r] ? frow2[500 + ii[r]] : zz;
        u1m[r] = iok[r] ? frow2[550 + ii[r]] : zz;
    }

    float m0 = -INFINITY, m1 = -INFINITY, den0 = 0.f, den1 = 0.f;
    float2 vac[4];
#pragma unroll
    for (int s = 0; s < 4; s++) vac[s] = zz;
    float2 e0t[2], e0m[2], e1t[2], e1m[2];
#pragma unroll
    for (int r = 0; r < 2; r++) { e0t[r] = zz; e0m[r] = zz; e1t[r] = zz; e1m[r] = zz; }

    float relA = 0.f, relB = 0.f;
    float2 kvA[4], vvA[4], mgA[2], kvB[4], vvB[4], mgB[2];

    // L2 prefetch of edge idx's k/v (1600 B, 14 lines) and msg (400 B, 5 lines)
    auto prefetch_edge = [&](int idx) {
        if (idx < deg) {
            int4 rec = d_edge[base + idx];
            if (lane < 14) {
                const char* kvp = (const char*)(d_fused + (size_t)rec.x * FW + 200);
                asm volatile("prefetch.global.L2 [%0];" :: "l"(kvp + lane * 128));
            } else if (lane < 19) {
                const char* mp = (const char*)(msg + (size_t)rec.y * 100);
                asm volatile("prefetch.global.L2 [%0];" :: "l"(mp + (lane - 14) * 128));
            }
        }
    };

    auto load_edge = [&](int idx, float& rel, float2* kv, float2* vv, float2* mg) {
        int4 rec = d_edge[base + idx];          // {src, eid, rel_bits, 0}
        int src = rec.x, eid = rec.y;
        rel = __int_as_float(rec.z);
        const float2* s2 = (const float2*)(d_fused + (size_t)src * FW);
#pragma unroll
        for (int s = 0; s < 4; s++) {
            kv[s] = jok[s] ? s2[100 + ji[s]] : zz;
            vv[s] = jok[s] ? s2[200 + ji[s]] : zz;
        }
        const float2* m2 = (const float2*)(msg + (size_t)eid * 100);
#pragma unroll
        for (int r = 0; r < 2; r++) mg[r] = iok[r] ? m2[ii[r]] : zz;
    };

    auto process = [&](float rel, const float2* kv, const float2* vv, const float2* mg) {
        float2 te[2];
        float a0 = 0.f, a1 = 0.f;
#pragma unroll
        for (int r = 0; r < 2; r++) {
            if (iok[r]) {
                int i2 = i2v[r];
                float y0 = __fadd_rn(__fmul_rn(rel, s_wt[i2]),     s_bt[i2]);
                float y1 = __fadd_rn(__fmul_rn(rel, s_wt[i2 + 1]), s_bt[i2 + 1]);
                te[r].x = cos_acc(y0);
                te[r].y = cos_acc(y1);
            } else te[r] = zz;
            a0 += te[r].x * u0t[r].x + te[r].y * u0t[r].y
                + mg[r].x * u0m[r].x + mg[r].y * u0m[r].y;
            a1 += te[r].x * u1t[r].x + te[r].y * u1t[r].y
                + mg[r].x * u1m[r].x + mg[r].y * u1m[r].y;
        }
#pragma unroll
        for (int s = 0; s < 4; s++) {
            float dp = qv[s].x * kv[s].x + qv[s].y * kv[s].y;
            if (jh1[s]) a1 += dp; else a0 += dp;
        }
#pragma unroll
        for (int o = 16; o > 0; o >>= 1) {
            a0 += __shfl_xor_sync(0xffffffffu, a0, o);
            a1 += __shfl_xor_sync(0xffffffffu, a1, o);
        }
        a0 *= 0.1f; a1 *= 0.1f;

        float nm0 = fmaxf(m0, a0), nm1 = fmaxf(m1, a1);
        float f0 = __expf(m0 - nm0), f1 = __expf(m1 - nm1);
        float w0 = __expf(a0 - nm0), w1 = __expf(a1 - nm1);
        m0 = nm0; m1 = nm1;
        den0 = den0 * f0 + w0;
        den1 = den1 * f1 + w1;
#pragma unroll
        for (int s = 0; s < 4; s++) {
            float f = jh1[s] ? f1 : f0, w = jh1[s] ? w1 : w0;
            vac[s].x = vac[s].x * f + w * vv[s].x;
            vac[s].y = vac[s].y * f + w * vv[s].y;
        }
#pragma unroll
        for (int r = 0; r < 2; r++) {
            e0t[r].x = e0t[r].x * f0 + w0 * te[r].x;  e0t[r].y = e0t[r].y * f0 + w0 * te[r].y;
            e0m[r].x = e0m[r].x * f0 + w0 * mg[r].x;  e0m[r].y = e0m[r].y * f0 + w0 * mg[r].y;
            e1t[r].x = e1t[r].x * f1 + w1 * te[r].x;  e1t[r].y = e1t[r].y * f1 + w1 * te[r].y;
            e1m[r].x = e1m[r].x * f1 + w1 * mg[r].x;  e1m[r].y = e1m[r].y * f1 + w1 * mg[r].y;
        }
    };

    if (deg > 0) {
        load_edge(0, relA, kvA, vvA, mgA);
        prefetch_edge(1);
        prefetch_edge(2);
    }
    int d = 0;
    while (d < deg) {
        if (d + 1 < deg) { load_edge(d + 1, relB, kvB, vvB, mgB); prefetch_edge(d + 3); }
        process(relA, kvA, vvA, mgA);
        if (++d >= deg) break;
        if (d + 1 < deg) { load_edge(d + 1, relA, kvA, vvA, mgA); prefetch_edge(d + 3); }
        process(relB, kvB, vvB, mgB);
        ++d;
    }

    float inv0 = 1.f / (den0 + 1e-16f), inv1 = 1.f / (den1 + 1e-16f);
    float2* out2 = (float2*)(out + (size_t)n * HC);
#pragma unroll
    for (int s = 0; s < 4; s++) {
        if (jok[s]) {
            float inv = jh1[s] ? inv1 : inv0;
            float2 sk = frow2[300 + ji[s]];
            out2[ji[s]] = make_float2(sk.x + vac[s].x * inv, sk.y + vac[s].y * inv);
        }
    }
    float2* ae2 = (float2*)(d_aggea + (size_t)n * 400);
#pragma unroll
    for (int r = 0; r < 2; r++) {
        if (iok[r]) {
            ae2[ii[r]]       = make_float2(e0t[r].x * inv0, e0t[r].y * inv0);
            ae2[50 + ii[r]]  = make_float2(e0m[r].x * inv0, e0m[r].y * inv0);
            ae2[100 + ii[r]] = make_float2(e1t[r].x * inv1, e1t[r].y * inv1);
            ae2[150 + ii[r]] = make_float2(e1m[r].x * inv1, e1m[r].y * inv1);
        }
    }
}

// ---------------- launch ----------------
extern "C" void kernel_launch(void* const* d_in, const int* in_sizes, int n_in,
                              void* d_out, int out_size)
{
    const float* x       = (const float*)d_in[0];
    const float* last_up = (const float*)d_in[1];
    const int*   ei      = (const int*)  d_in[2];
    const float* tarr    = (const float*)d_in[3];
    const float* msg     = (const float*)d_in[4];
    const float* w_time  = (const float*)d_in[5];
    const float* b_time  = (const float*)d_in[6];
    const float* Wq      = (const float*)d_in[7];
    const float* bq      = (const float*)d_in[8];
    const float* Wk      = (const float*)d_in[9];
    const float* bk      = (const float*)d_in[10];
    const float* Wv      = (const float*)d_in[11];
    const float* bv      = (const float*)d_in[12];
    const float* We      = (const float*)d_in[13];
    const float* Ws      = (const float*)d_in[14];
    const float* bs      = (const float*)d_in[15];
    float* out = (float*)d_out;

    float *fused_p, *ae_p, *w_p, *b_p;
    cudaGetSymbolAddress((void**)&fused_p, d_fused);
    cudaGetSymbolAddress((void**)&ae_p,    d_aggea);
    cudaGetSymbolAddress((void**)&w_p,     d_W);
    cudaGetSymbolAddress((void**)&b_p,     d_bias);

    cudaFuncSetAttribute(gemm_tf32_k,
                         cudaFuncAttributeMaxDynamicSharedMemorySize, GEMM_SMEM);
    cudaFuncSetAttribute(gemm_fin_k,
                         cudaFuncAttributeMaxDynamicSharedMemorySize, GEMM_SMEM);

    pack_w_k<<<(100 * FW + 255) / 256, 256>>>(Wq, Wk, Wv, Ws, We);   // 0
    pack_b_k<<<(FW + 255) / 256, 256>>>(bq, bk, bv, bs, We);         // 1
    zero_cnt_k<<<(NN + 255) / 256, 256>>>();                         // 2

    const int gx = (NN + TBM - 1) / TBM;   // 782
    // 3 (profiled slot): mega GEMM
    gemm_tf32_k<<<gx, 256, GEMM_SMEM>>>(x, 100, w_p, FW, fused_p, FW,
                                        NN, FW, b_p);

    // CSR by dst (+ per-edge record precompute in scatter)
    hist_k<<<(EE + 255) / 256, 256>>>(ei);
    int nb = (NN + 1023) / 1024;
    scan1_k<<<nb, 1024>>>();
    scan2_k<<<1, 128>>>(nb);
    scan3_k<<<(NN + 255) / 256, 256>>>();
    scatter_k<<<(EE + 255) / 256, 256>>>(ei, tarr, last_up);

    // single-pass attention (warp per node)
    attn_k<<<(NN + 3) / 4, 128>>>(msg, w_time, b_time, out);

    // finals: one fused K=200 accumulate per head
    for (int h = 0; h < 2; h++) {
        gemm_fin_k<<<gx, 256, GEMM_SMEM>>>(ae_p + h * 200, We + h * 100,
                                           out + h * 100);
    }
}

// round 12
// speedup vs baseline: 1.0758x; 1.0428x over previous
#include <cuda_runtime.h>
#include <math.h>
#include <stdint.h>

#define NN 100000
#define EE 400000
#define HC 200      // HEADS*OUT_CH
#define CC 100      // OUT_CH
#define TD 100      // TIME_DIM
#define FW 1200     // fused width: q(200)|k(200)|v(200)|skip(200)|u(400)
#define TBM 128
#define TBN 64
#define BST 72
#define AST 108
#define GEMM_SMEM ((TBM * AST + 104 * BST) * 4)

// ---------------- scratch (device globals; allocation-free) ----------------
__device__ __align__(16) float d_fused[(size_t)NN * FW];   // 480 MB
__device__ __align__(16) float d_aggea[(size_t)NN * 400];  // 160 MB
__device__ __align__(16) float d_W[100 * FW];
__device__ __align__(16) float d_bias[FW];
__device__ __align__(16) int4  d_edge[EE];                 // {src, eid, rel_bits, 0}
__device__ int d_cnt[NN];
__device__ int d_rowptr[NN + 1];
__device__ int d_cursor[NN];
__device__ int d_tmpscan[NN];
__device__ int d_bsum[256];
__device__ int d_boff[256];

// ---------------- accurate cos, fp32-only Cody-Waite reduction ----------------
__device__ __forceinline__ float cos_acc(float y) {
    float k = rintf(y * 0.15915494309189535f);
    float r = fmaf(k, -6.2831854820251465f, y);
    r = fmaf(k, 1.7484556000744e-7f, r);
    return cosf(r);
}

__device__ __forceinline__ uint32_t f2tf32(float f) {
    uint32_t u;
    asm("cvt.rna.tf32.f32 %0, %1;" : "=r"(u) : "f"(f));
    return u;
}

__device__ __forceinline__ void mma_tf32(float c[4],
                                         uint32_t a0, uint32_t a1, uint32_t a2, uint32_t a3,
                                         uint32_t b0, uint32_t b1) {
    asm volatile(
        "mma.sync.aligned.m16n8k8.row.col.f32.tf32.tf32.f32 "
        "{%0,%1,%2,%3}, {%4,%5,%6,%7}, {%8,%9}, {%0,%1,%2,%3};"
        : "+f"(c[0]), "+f"(c[1]), "+f"(c[2]), "+f"(c[3])
        : "r"(a0), "r"(a1), "r"(a2), "r"(a3), "r"(b0), "r"(b1));
}

// ---------------- weight packing ----------------
__global__ void pack_w_k(const float* __restrict__ Wq, const float* __restrict__ Wk,
                         const float* __restrict__ Wv, const float* __restrict__ Ws,
                         const float* __restrict__ We) {
    int idx = blockIdx.x * blockDim.x + threadIdx.x;
    if (idx >= 100 * FW) return;
    int k = idx / FW;
    int c = idx % FW;
    float val;
    if (c < 200)       val = Wq[k * HC + c];
    else if (c < 400)  val = Wk[k * HC + (c - 200)];
    else if (c < 600)  val = Wv[k * HC + (c - 400)];
    else if (c < 800)  val = Ws[k * HC + (c - 600)];
    else {
        int c2 = c - 800;
        int h = c2 / 200, i = c2 % 200;
        float s = 0.f;
        for (int cc = 0; cc < CC; cc++)
            s += Wq[k * HC + h * CC + cc] * We[i * HC + h * CC + cc];
        val = s;
    }
    d_W[idx] = val;
}

__global__ void pack_b_k(const float* __restrict__ bq, const float* __restrict__ bk,
                         const float* __restrict__ bv, const float* __restrict__ bs,
                         const float* __restrict__ We) {
    int c = blockIdx.x * blockDim.x + threadIdx.x;
    if (c >= FW) return;
    float val;
    if (c < 200)       val = bq[c];
    else if (c < 400)  val = bk[c - 200];
    else if (c < 600)  val = bv[c - 400];
    else if (c < 800)  val = bs[c - 600];
    else {
        int c2 = c - 800;
        int h = c2 / 200, i = c2 % 200;
        float s = 0.f;
        for (int cc = 0; cc < CC; cc++)
            s += bq[h * CC + cc] * We[i * HC + h * CC + cc];
        val = s;
    }
    d_bias[c] = val;
}

// ---------------- tf32 tensor-core GEMM (K=100, A resident) ----------------
__global__ void __launch_bounds__(256) gemm_tf32_k(
    const float* __restrict__ A, int lda,
    const float* __restrict__ B, int ldb,
    float* __restrict__ C, int ldc,
    int M, int Ncol,
    const float* __restrict__ bias)
{
    extern __shared__ uint32_t sm[];
    uint32_t* As = sm;               // [TBM][AST]
    uint32_t* Bs = sm + TBM * AST;   // [104][BST]

    const int t    = threadIdx.x;
    const int lane = t & 31;
    const int wid  = t >> 5;
    const int m0   = blockIdx.x * TBM;
    const int wm   = (wid >> 1) * 32;
    const int wn   = (wid & 1) * 32;

    for (int i = t; i < TBM * 8; i += 256) {
        int r = i >> 3;
        As[r * AST + 100 + (i & 7)] = 0;
    }
    for (int i = t; i < 4 * BST; i += 256)
        Bs[(100 + i / BST) * BST + (i % BST)] = 0;

    for (int i = t; i < TBM * 100; i += 256) {
        int r = i / 100, c = i - r * 100;
        int gr = m0 + r;
        float v = (gr < M) ? A[(size_t)gr * lda + c] : 0.f;
        As[r * AST + c] = f2tf32(v);
    }

    const int nch = (Ncol + TBN - 1) / TBN;
    float pb[25];
#pragma unroll
    for (int j = 0; j < 25; j++) {
        int i = t + j * 256;
        int k = i >> 6, n = i & 63;
        pb[j] = (n < Ncol) ? B[(size_t)k * ldb + n] : 0.f;
    }
    __syncthreads();

    const int arow = wm + (lane >> 2);
    const int acol = lane & 3;
    const int brow = lane & 3;
    const int bcol = wn + (lane >> 2);

    for (int cidx = 0; cidx < nch; cidx++) {
#pragma unroll
        for (int j = 0; j < 25; j++) {
            int i = t + j * 256;
            int k = i >> 6, n = i & 63;
            Bs[k * BST + n] = f2tf32(pb[j]);
        }
        __syncthreads();

        const int n0 = cidx * TBN;
        if (cidx + 1 < nch) {
            int n0n = n0 + TBN;
#pragma unroll
            for (int j = 0; j < 25; j++) {
                int i = t + j * 256;
                int k = i >> 6, n = i & 63;
                int gc = n0n + n;
                pb[j] = (gc < Ncol) ? B[(size_t)k * ldb + gc] : 0.f;
            }
        }

        float acc[2][4][4];
#pragma unroll
        for (int mt = 0; mt < 2; mt++)
#pragma unroll
            for (int nt = 0; nt < 4; nt++)
#pragma unroll
                for (int r = 0; r < 4; r++) acc[mt][nt][r] = 0.f;

#pragma unroll
        for (int ks = 0; ks < 13; ks++) {
            const int k0 = ks * 8;
            uint32_t a[2][4];
#pragma unroll
            for (int mt = 0; mt < 2; mt++) {
                int r = arow + mt * 16;
                a[mt][0] = As[r * AST + k0 + acol];
                a[mt][1] = As[(r + 8) * AST + k0 + acol];
                a[mt][2] = As[r * AST + k0 + acol + 4];
                a[mt][3] = As[(r + 8) * AST + k0 + acol + 4];
            }
            uint32_t b[4][2];
#pragma unroll
            for (int nt = 0; nt < 4; nt++) {
                b[nt][0] = Bs[(k0 + brow) * BST + bcol + nt * 8];
                b[nt][1] = Bs[(k0 + brow + 4) * BST + bcol + nt * 8];
            }
#pragma unroll
            for (int mt = 0; mt < 2; mt++)
#pragma unroll
                for (int nt = 0; nt < 4; nt++)
                    mma_tf32(acc[mt][nt], a[mt][0], a[mt][1], a[mt][2], a[mt][3],
                             b[nt][0], b[nt][1]);
        }

#pragma unroll
        for (int mt = 0; mt < 2; mt++) {
            int rbase = m0 + wm + mt * 16 + (lane >> 2);
#pragma unroll
            for (int half = 0; half < 2; half++) {
                int r = rbase + half * 8;
                if (r < M) {
#pragma unroll
                    for (int nt = 0; nt < 4; nt++) {
                        int col = n0 + wn + nt * 8 + (lane & 3) * 2;
                        if (col < Ncol) {
                            float v0 = acc[mt][nt][half * 2 + 0];
                            float v1 = acc[mt][nt][half * 2 + 1];
                            if (bias) { v0 += bias[col]; v1 += bias[col + 1]; }
                            *(float2*)(C + (size_t)r * ldc + col) = make_float2(v0, v1);
                        }
                    }
                }
            }
        }
        __syncthreads();
    }
}

// ---------------- finals: C += A[:,0:100]@B0 + A[:,100:200]@B1, Ncol=100 ----
__global__ void __launch_bounds__(256) gemm_fin_k(
    const float* __restrict__ A,
    const float* __restrict__ B,
    float* __restrict__ C)
{
    extern __shared__ uint32_t sm[];
    uint32_t* As = sm;               // [TBM][AST]
    uint32_t* Bs = sm + TBM * AST;   // [104][BST]

    const int t    = threadIdx.x;
    const int lane = t & 31;
    const int wid  = t >> 5;
    const int m0   = blockIdx.x * TBM;
    const int wm   = (wid >> 1) * 32;
    const int wn   = (wid & 1) * 32;

    for (int i = t; i < TBM * 8; i += 256) {
        int r = i >> 3;
        As[r * AST + 100 + (i & 7)] = 0;
    }
    for (int i = t; i < 4 * BST; i += 256)
        Bs[(100 + i / BST) * BST + (i % BST)] = 0;

    const int arow = wm + (lane >> 2);
    const int acol = lane & 3;
    const int brow = lane & 3;
    const int bcol = wn + (lane >> 2);

    for (int cidx = 0; cidx < 2; cidx++) {
        const int n0 = cidx * TBN;

        float acc[2][4][4];
#pragma unroll
        for (int mt = 0; mt < 2; mt++)
#pragma unroll
            for (int nt = 0; nt < 4; nt++)
#pragma unroll
                for (int r = 0; r < 4; r++) acc[mt][nt][r] = 0.f;

        for (int kh = 0; kh < 2; kh++) {
            __syncthreads();
            const float* Ap = A + kh * 100;
            const float* Bp = B + (size_t)(kh * 100) * HC;
            for (int i = t; i < TBM * 100; i += 256) {
                int r = i / 100, c = i - r * 100;
                int gr = m0 + r;
                float v = (gr < NN) ? Ap[(size_t)gr * 400 + c] : 0.f;
                As[r * AST + c] = f2tf32(v);
            }
            for (int i = t; i < 100 * TBN; i += 256) {
                int k = i >> 6, n = i & 63;
                int gc = n0 + n;
                Bs[k * BST + n] = f2tf32((gc < CC) ? Bp[(size_t)k * HC + gc] : 0.f);
            }
            __syncthreads();

#pragma unroll
            for (int ks = 0; ks < 13; ks++) {
                const int k0 = ks * 8;
                uint32_t a[2][4];
#pragma unroll
                for (int mt = 0; mt < 2; mt++) {
                    int r = arow + mt * 16;
                    a[mt][0] = As[r * AST + k0 + acol];
                    a[mt][1] = As[(r + 8) * AST + k0 + acol];
                    a[mt][2] = As[r * AST + k0 + acol + 4];
                    a[mt][3] = As[(r + 8) * AST + k0 + acol + 4];
                }
                uint32_t b[4][2];
#pragma unroll
                for (int nt = 0; nt < 4; nt++) {
                    b[nt][0] = Bs[(k0 + brow) * BST + bcol + nt * 8];
                    b[nt][1] = Bs[(k0 + brow + 4) * BST + bcol + nt * 8];
                }
#pragma unroll
                for (int mt = 0; mt < 2; mt++)
#pragma unroll
                    for (int nt = 0; nt < 4; nt++)
                        mma_tf32(acc[mt][nt], a[mt][0], a[mt][1], a[mt][2], a[mt][3],
                                 b[nt][0], b[nt][1]);
            }
        }

#pragma unroll
        for (int mt = 0; mt < 2; mt++) {
            int rbase = m0 + wm + mt * 16 + (lane >> 2);
#pragma unroll
            for (int half = 0; half < 2; half++) {
                int r = rbase + half * 8;
                if (r < NN) {
#pragma unroll
                    for (int nt = 0; nt < 4; nt++) {
                        int col = n0 + wn + nt * 8 + (lane & 3) * 2;
                        if (col < CC) {
                            float* cp = C + (size_t)r * HC + col;
                            float v0 = acc[mt][nt][half * 2 + 0] + cp[0];
                            float v1 = acc[mt][nt][half * 2 + 1] + cp[1];
                            *(float2*)cp = make_float2(v0, v1);
                        }
                    }
                }
            }
        }
    }
}

// ---------------- CSR build ----------------
__global__ void zero_cnt_k() {
    int i = blockIdx.x * blockDim.x + threadIdx.x;
    if (i < NN) d_cnt[i] = 0;
}
__global__ void hist_k(const int* __restrict__ ei) {
    int e = blockIdx.x * blockDim.x + threadIdx.x;
    if (e < EE) atomicAdd(&d_cnt[ei[EE + e]], 1);
}
__global__ void scan1_k() {
    __shared__ int ws[32];
    int i = blockIdx.x * 1024 + threadIdx.x;
    int v = (i < NN) ? d_cnt[i] : 0;
    int lane = threadIdx.x & 31, wid = threadIdx.x >> 5;
    int s = v;
#pragma unroll
    for (int d = 1; d < 32; d <<= 1) {
        int tv = __shfl_up_sync(0xffffffffu, s, d);
        if (lane >= d) s += tv;
    }
    if (lane == 31) ws[wid] = s;
    __syncthreads();
    if (wid == 0) {
        int t2 = ws[lane];
#pragma unroll
        for (int d = 1; d < 32; d <<= 1) {
            int tv = __shfl_up_sync(0xffffffffu, t2, d);
            if (lane >= d) t2 += tv;
        }
        ws[lane] = t2;
    }
    __syncthreads();
    int add = (wid > 0) ? ws[wid - 1] : 0;
    s += add;
    if (i < NN) d_tmpscan[i] = s;
    if (threadIdx.x == 1023) d_bsum[blockIdx.x] = s;
}
// parallel exclusive scan of block sums (nb <= 128)
__global__ void scan2_k(int nb) {
    __shared__ int sh[128];
    int t = threadIdx.x;
    int v = (t < nb) ? d_bsum[t] : 0;
    sh[t] = v;
    __syncthreads();
#pragma unroll
    for (int o = 1; o < 128; o <<= 1) {
        int u = (t >= o) ? sh[t - o] : 0;
        __syncthreads();
        sh[t] += u;
        __syncthreads();
    }
    if (t < nb) d_boff[t] = sh[t] - v;   // exclusive prefix
}
__global__ void scan3_k() {
    int i = blockIdx.x * blockDim.x + threadIdx.x;
    if (i < NN) {
        int rp = (i == 0) ? 0 : (d_tmpscan[i - 1] + d_boff[(i - 1) >> 10]);
        d_rowptr[i] = rp;
        d_cursor[i] = rp;
        if (i == NN - 1) d_rowptr[NN] = d_tmpscan[i] + d_boff[i >> 10];
    }
}
// scatter + precompute per-edge record {src, eid, rel}
__global__ void scatter_k(const int* __restrict__ ei,
                          const float* __restrict__ tarr,
                          const float* __restrict__ lastup) {
    int e = blockIdx.x * blockDim.x + threadIdx.x;
    if (e < EE) {
        int src = ei[e];
        int dst = ei[EE + e];
        float rel = fabsf(__ldg(lastup + src) - __ldg(tarr + e));
        int p = atomicAdd(&d_cursor[dst], 1);
        d_edge[p] = make_int4(src, e, __float_as_int(rel), 0);
    }
}

// ---------------- fused single-pass attention (no-max softmax) ----------------
// warp per node; 2-stage register pipeline; shift-invariant softmax without
// running max (alpha magnitudes bounded ~|10|, exp safe in fp32).
__global__ void __launch_bounds__(128) attn_k(
    const float* __restrict__ msg,
    const float* __restrict__ w_time,
    const float* __restrict__ b_time,
    float* __restrict__ out)
{
    __shared__ float s_wt[TD], s_bt[TD];
    for (int i = threadIdx.x; i < TD; i += 128) { s_wt[i] = w_time[i]; s_bt[i] = b_time[i]; }
    __syncthreads();

    int warp = (blockIdx.x * 128 + threadIdx.x) >> 5;
    int lane = threadIdx.x & 31;
    if (warp >= NN) return;
    const int n = warp;
    const int base = d_rowptr[n];
    const int deg  = d_rowptr[n + 1] - base;

    const float2* frow2 = (const float2*)(d_fused + (size_t)n * FW);

    bool jok[4], jh1[4];
    int  ji[4];
#pragma unroll
    for (int s = 0; s < 4; s++) {
        int j2 = s * 64 + lane * 2;
        jok[s] = j2 < 200; jh1[s] = j2 >= 100; ji[s] = s * 32 + lane;
    }
    bool iok[2]; int ii[2]; int i2v[2];
#pragma unroll
    for (int r = 0; r < 2; r++) {
        int i2 = r * 64 + lane * 2;
        iok[r] = i2 < 100; ii[r] = r * 32 + lane; i2v[r] = i2;
    }

    const float2 zz = make_float2(0.f, 0.f);
    float2 qv[4];
#pragma unroll
    for (int s = 0; s < 4; s++) qv[s] = jok[s] ? frow2[ji[s]] : zz;
    float2 u0t[2], u0m[2], u1t[2], u1m[2];
#pragma unroll
    for (int r = 0; r < 2; r++) {
        u0t[r] = iok[r] ? frow2[400 + ii[r]] : zz;
        u0m[r] = iok[r] ? frow2[450 + ii[r]] : zz;
        u1t[r] = iok[r] ? frow2[500 + ii[r]] : zz;
        u1m[r] = iok[r] ? frow2[550 + ii[r]] : zz;
    }

    float den0 = 0.f, den1 = 0.f;
    float2 vac[4];
#pragma unroll
    for (int s = 0; s < 4; s++) vac[s] = zz;
    float2 e0t[2], e0m[2], e1t[2], e1m[2];
#pragma unroll
    for (int r = 0; r < 2; r++) { e0t[r] = zz; e0m[r] = zz; e1t[r] = zz; e1m[r] = zz; }

    float relA = 0.f, relB = 0.f;
    float2 kvA[4], vvA[4], mgA[2], kvB[4], vvB[4], mgB[2];

    auto load_edge = [&](int idx, float& rel, float2* kv, float2* vv, float2* mg) {
        int4 rec = d_edge[base + idx];          // {src, eid, rel_bits, 0}
        int src = rec.x, eid = rec.y;
        rel = __int_as_float(rec.z);
        const float2* s2 = (const float2*)(d_fused + (size_t)src * FW);
#pragma unroll
        for (int s = 0; s < 4; s++) {
            kv[s] = jok[s] ? s2[100 + ji[s]] : zz;
            vv[s] = jok[s] ? s2[200 + ji[s]] : zz;
        }
        const float2* m2 = (const float2*)(msg + (size_t)eid * 100);
#pragma unroll
        for (int r = 0; r < 2; r++) mg[r] = iok[r] ? m2[ii[r]] : zz;
    };

    auto process = [&](float rel, const float2* kv, const float2* vv, const float2* mg) {
        float2 te[2];
        float a0 = 0.f, a1 = 0.f;
#pragma unroll
        for (int r = 0; r < 2; r++) {
            if (iok[r]) {
                int i2 = i2v[r];
                float y0 = __fadd_rn(__fmul_rn(rel, s_wt[i2]),     s_bt[i2]);
                float y1 = __fadd_rn(__fmul_rn(rel, s_wt[i2 + 1]), s_bt[i2 + 1]);
                te[r].x = cos_acc(y0);
                te[r].y = cos_acc(y1);
            } else te[r] = zz;
            a0 += te[r].x * u0t[r].x + te[r].y * u0t[r].y
                + mg[r].x * u0m[r].x + mg[r].y * u0m[r].y;
            a1 += te[r].x * u1t[r].x + te[r].y * u1t[r].y
                + mg[r].x * u1m[r].x + mg[r].y * u1m[r].y;
        }
#pragma unroll
        for (int s = 0; s < 4; s++) {
            float dp = qv[s].x * kv[s].x + qv[s].y * kv[s].y;
            if (jh1[s]) a1 += dp; else a0 += dp;
        }
#pragma unroll
        for (int o = 16; o > 0; o >>= 1) {
            a0 += __shfl_xor_sync(0xffffffffu, a0, o);
            a1 += __shfl_xor_sync(0xffffffffu, a1, o);
        }

        // no-max softmax weights (alpha bounded; exp safe in fp32)
        float w0 = __expf(a0 * 0.1f);
        float w1 = __expf(a1 * 0.1f);
        den0 += w0;
        den1 += w1;
#pragma unroll
        for (int s = 0; s < 4; s++) {
            float w = jh1[s] ? w1 : w0;
            vac[s].x += w * vv[s].x;
            vac[s].y += w * vv[s].y;
        }
#pragma unroll
        for (int r = 0; r < 2; r++) {
            e0t[r].x += w0 * te[r].x;  e0t[r].y += w0 * te[r].y;
            e0m[r].x += w0 * mg[r].x;  e0m[r].y += w0 * mg[r].y;
            e1t[r].x += w1 * te[r].x;  e1t[r].y += w1 * te[r].y;
            e1m[r].x += w1 * mg[r].x;  e1m[r].y += w1 * mg[r].y;
        }
    };

    if (deg > 0) load_edge(0, relA, kvA, vvA, mgA);
    int d = 0;
    while (d < deg) {
        if (d + 1 < deg) load_edge(d + 1, relB, kvB, vvB, mgB);
        process(relA, kvA, vvA, mgA);
        if (++d >= deg) break;
        if (d + 1 < deg) load_edge(d + 1, relA, kvA, vvA, mgA);
        process(relB, kvB, vvB, mgB);
        ++d;
    }

    float inv0 = 1.f / (den0 + 1e-16f), inv1 = 1.f / (den1 + 1e-16f);
    float2* out2 = (float2*)(out + (size_t)n * HC);
#pragma unroll
    for (int s = 0; s < 4; s++) {
        if (jok[s]) {
            float inv = jh1[s] ? inv1 : inv0;
            float2 sk = frow2[300 + ji[s]];
            out2[ji[s]] = make_float2(sk.x + vac[s].x * inv, sk.y + vac[s].y * inv);
        }
    }
    float2* ae2 = (float2*)(d_aggea + (size_t)n * 400);
#pragma unroll
    for (int r = 0; r < 2; r++) {
        if (iok[r]) {
            ae2[ii[r]]       = make_float2(e0t[r].x * inv0, e0t[r].y * inv0);
            ae2[50 + ii[r]]  = make_float2(e0m[r].x * inv0, e0m[r].y * inv0);
            ae2[100 + ii[r]] = make_float2(e1t[r].x * inv1, e1t[r].y * inv1);
            ae2[150 + ii[r]] = make_float2(e1m[r].x * inv1, e1m[r].y * inv1);
        }
    }
}

// ---------------- launch ----------------
extern "C" void kernel_launch(void* const* d_in, const int* in_sizes, int n_in,
                              void* d_out, int out_size)
{
    const float* x       = (const float*)d_in[0];
    const float* last_up = (const float*)d_in[1];
    const int*   ei      = (const int*)  d_in[2];
    const float* tarr    = (const float*)d_in[3];
    const float* msg     = (const float*)d_in[4];
    const float* w_time  = (const float*)d_in[5];
    const float* b_time  = (const float*)d_in[6];
    const float* Wq      = (const float*)d_in[7];
    const float* bq      = (const float*)d_in[8];
    const float* Wk      = (const float*)d_in[9];
    const float* bk      = (const float*)d_in[10];
    const float* Wv      = (const float*)d_in[11];
    const float* bv      = (const float*)d_in[12];
    const float* We      = (const float*)d_in[13];
    const float* Ws      = (const float*)d_in[14];
    const float* bs      = (const float*)d_in[15];
    float* out = (float*)d_out;

    float *fused_p, *ae_p, *w_p, *b_p;
    cudaGetSymbolAddress((void**)&fused_p, d_fused);
    cudaGetSymbolAddress((void**)&ae_p,    d_aggea);
    cudaGetSymbolAddress((void**)&w_p,     d_W);
    cudaGetSymbolAddress((void**)&b_p,     d_bias);

    cudaFuncSetAttribute(gemm_tf32_k,
                         cudaFuncAttributeMaxDynamicSharedMemorySize, GEMM_SMEM);
    cudaFuncSetAttribute(gemm_fin_k,
                         cudaFuncAttributeMaxDynamicSharedMemorySize, GEMM_SMEM);

    pack_w_k<<<(100 * FW + 255) / 256, 256>>>(Wq, Wk, Wv, Ws, We);   // 0
    pack_b_k<<<(FW + 255) / 256, 256>>>(bq, bk, bv, bs, We);         // 1
    zero_cnt_k<<<(NN + 255) / 256, 256>>>();                         // 2

    const int gx = (NN + TBM - 1) / TBM;   // 782
    // 3 (profiled slot): mega GEMM
    gemm_tf32_k<<<gx, 256, GEMM_SMEM>>>(x, 100, w_p, FW, fused_p, FW,
                                        NN, FW, b_p);

    // CSR by dst (+ per-edge record precompute in scatter)
    hist_k<<<(EE + 255) / 256, 256>>>(ei);
    int nb = (NN + 1023) / 1024;
    scan1_k<<<nb, 1024>>>();
    scan2_k<<<1, 128>>>(nb);
    scan3_k<<<(NN + 255) / 256, 256>>>();
    scatter_k<<<(EE + 255) / 256, 256>>>(ei, tarr, last_up);

    // single-pass attention (warp per node)
    attn_k<<<(NN + 3) / 4, 128>>>(msg, w_time, b_time, out);

    // finals: one fused K=200 accumulate per head
    for (int h = 0; h < 2; h++) {
        gemm_fin_k<<<gx, 256, GEMM_SMEM>>>(ae_p + h * 200, We + h * 100,
                                           out + h * 100);
    }
}

// round 13
// speedup vs baseline: 1.0841x; 1.0076x over previous
#include <cuda_runtime.h>
#include <math.h>
#include <stdint.h>

#define NN 100000
#define EE 400000
#define HC 200      // HEADS*OUT_CH
#define CC 100      // OUT_CH
#define TD 100      // TIME_DIM
#define FW 1200     // fused width: q(200)|k(200)|v(200)|skip(200)|u(400)
#define TBM 128
#define TBN 64
#define BST 72
#define AST 108
#define GEMM_SMEM ((TBM * AST + 104 * BST) * 4)

// ---------------- scratch (device globals; allocation-free) ----------------
__device__ __align__(16) float d_fused[(size_t)NN * FW];   // 480 MB
__device__ __align__(16) float d_aggea[(size_t)NN * 400];  // 160 MB
__device__ __align__(16) float d_W[100 * FW];
__device__ __align__(16) float d_bias[FW];
__device__ __align__(16) int4  d_edge[EE];                 // {src, eid, rel_bits, 0}
__device__ int d_cnt[NN];
__device__ int d_rowptr[NN + 1];
__device__ int d_cursor[NN];
__device__ int d_tmpscan[NN];
__device__ int d_bsum[256];
__device__ int d_boff[256];

// ---------------- accurate cos, fp32-only Cody-Waite reduction ----------------
__device__ __forceinline__ float cos_acc(float y) {
    float k = rintf(y * 0.15915494309189535f);
    float r = fmaf(k, -6.2831854820251465f, y);
    r = fmaf(k, 1.7484556000744e-7f, r);
    return cosf(r);
}

__device__ __forceinline__ uint32_t f2tf32(float f) {
    uint32_t u;
    asm("cvt.rna.tf32.f32 %0, %1;" : "=r"(u) : "f"(f));
    return u;
}

__device__ __forceinline__ void mma_tf32(float c[4],
                                         uint32_t a0, uint32_t a1, uint32_t a2, uint32_t a3,
                                         uint32_t b0, uint32_t b1) {
    asm volatile(
        "mma.sync.aligned.m16n8k8.row.col.f32.tf32.tf32.f32 "
        "{%0,%1,%2,%3}, {%4,%5,%6,%7}, {%8,%9}, {%0,%1,%2,%3};"
        : "+f"(c[0]), "+f"(c[1]), "+f"(c[2]), "+f"(c[3])
        : "r"(a0), "r"(a1), "r"(a2), "r"(a3), "r"(b0), "r"(b1));
}

// ---------------- weight packing ----------------
__global__ void pack_w_k(const float* __restrict__ Wq, const float* __restrict__ Wk,
                         const float* __restrict__ Wv, const float* __restrict__ Ws,
                         const float* __restrict__ We) {
    int idx = blockIdx.x * blockDim.x + threadIdx.x;
    if (idx >= 100 * FW) return;
    int k = idx / FW;
    int c = idx % FW;
    float val;
    if (c < 200)       val = Wq[k * HC + c];
    else if (c < 400)  val = Wk[k * HC + (c - 200)];
    else if (c < 600)  val = Wv[k * HC + (c - 400)];
    else if (c < 800)  val = Ws[k * HC + (c - 600)];
    else {
        int c2 = c - 800;
        int h = c2 / 200, i = c2 % 200;
        float s = 0.f;
        for (int cc = 0; cc < CC; cc++)
            s += Wq[k * HC + h * CC + cc] * We[i * HC + h * CC + cc];
        val = s;
    }
    d_W[idx] = val;
}

__global__ void pack_b_k(const float* __restrict__ bq, const float* __restrict__ bk,
                         const float* __restrict__ bv, const float* __restrict__ bs,
                         const float* __restrict__ We) {
    int c = blockIdx.x * blockDim.x + threadIdx.x;
    if (c >= FW) return;
    float val;
    if (c < 200)       val = bq[c];
    else if (c < 400)  val = bk[c - 200];
    else if (c < 600)  val = bv[c - 400];
    else if (c < 800)  val = bs[c - 600];
    else {
        int c2 = c - 800;
        int h = c2 / 200, i = c2 % 200;
        float s = 0.f;
        for (int cc = 0; cc < CC; cc++)
            s += bq[h * CC + cc] * We[i * HC + h * CC + cc];
        val = s;
    }
    d_bias[c] = val;
}

// ---------------- tf32 tensor-core GEMM (K=100, A resident) ----------------
__global__ void __launch_bounds__(256) gemm_tf32_k(
    const float* __restrict__ A, int lda,
    const float* __restrict__ B, int ldb,
    float* __restrict__ C, int ldc,
    int M, int Ncol,
    const float* __restrict__ bias)
{
    extern __shared__ uint32_t sm[];
    uint32_t* As = sm;               // [TBM][AST]
    uint32_t* Bs = sm + TBM * AST;   // [104][BST]

    const int t    = threadIdx.x;
    const int lane = t & 31;
    const int wid  = t >> 5;
    const int m0   = blockIdx.x * TBM;
    const int wm   = (wid >> 1) * 32;
    const int wn   = (wid & 1) * 32;

    for (int i = t; i < TBM * 8; i += 256) {
        int r = i >> 3;
        As[r * AST + 100 + (i & 7)] = 0;
    }
    for (int i = t; i < 4 * BST; i += 256)
        Bs[(100 + i / BST) * BST + (i % BST)] = 0;

    for (int i = t; i < TBM * 100; i += 256) {
        int r = i / 100, c = i - r * 100;
        int gr = m0 + r;
        float v = (gr < M) ? A[(size_t)gr * lda + c] : 0.f;
        As[r * AST + c] = f2tf32(v);
    }

    const int nch = (Ncol + TBN - 1) / TBN;
    float pb[25];
#pragma unroll
    for (int j = 0; j < 25; j++) {
        int i = t + j * 256;
        int k = i >> 6, n = i & 63;
        pb[j] = (n < Ncol) ? B[(size_t)k * ldb + n] : 0.f;
    }
    __syncthreads();

    const int arow = wm + (lane >> 2);
    const int acol = lane & 3;
    const int brow = lane & 3;
    const int bcol = wn + (lane >> 2);

    for (int cidx = 0; cidx < nch; cidx++) {
#pragma unroll
        for (int j = 0; j < 25; j++) {
            int i = t + j * 256;
            int k = i >> 6, n = i & 63;
            Bs[k * BST + n] = f2tf32(pb[j]);
        }
        __syncthreads();

        const int n0 = cidx * TBN;
        if (cidx + 1 < nch) {
            int n0n = n0 + TBN;
#pragma unroll
            for (int j = 0; j < 25; j++) {
                int i = t + j * 256;
                int k = i >> 6, n = i & 63;
                int gc = n0n + n;
                pb[j] = (gc < Ncol) ? B[(size_t)k * ldb + gc] : 0.f;
            }
        }

        float acc[2][4][4];
#pragma unroll
        for (int mt = 0; mt < 2; mt++)
#pragma unroll
            for (int nt = 0; nt < 4; nt++)
#pragma unroll
                for (int r = 0; r < 4; r++) acc[mt][nt][r] = 0.f;

#pragma unroll
        for (int ks = 0; ks < 13; ks++) {
            const int k0 = ks * 8;
            uint32_t a[2][4];
#pragma unroll
            for (int mt = 0; mt < 2; mt++) {
                int r = arow + mt * 16;
                a[mt][0] = As[r * AST + k0 + acol];
                a[mt][1] = As[(r + 8) * AST + k0 + acol];
                a[mt][2] = As[r * AST + k0 + acol + 4];
                a[mt][3] = As[(r + 8) * AST + k0 + acol + 4];
            }
            uint32_t b[4][2];
#pragma unroll
            for (int nt = 0; nt < 4; nt++) {
                b[nt][0] = Bs[(k0 + brow) * BST + bcol + nt * 8];
                b[nt][1] = Bs[(k0 + brow + 4) * BST + bcol + nt * 8];
            }
#pragma unroll
            for (int mt = 0; mt < 2; mt++)
#pragma unroll
                for (int nt = 0; nt < 4; nt++)
                    mma_tf32(acc[mt][nt], a[mt][0], a[mt][1], a[mt][2], a[mt][3],
                             b[nt][0], b[nt][1]);
        }

#pragma unroll
        for (int mt = 0; mt < 2; mt++) {
            int rbase = m0 + wm + mt * 16 + (lane >> 2);
#pragma unroll
            for (int half = 0; half < 2; half++) {
                int r = rbase + half * 8;
                if (r < M) {
#pragma unroll
                    for (int nt = 0; nt < 4; nt++) {
                        int col = n0 + wn + nt * 8 + (lane & 3) * 2;
                        if (col < Ncol) {
                            float v0 = acc[mt][nt][half * 2 + 0];
                            float v1 = acc[mt][nt][half * 2 + 1];
                            if (bias) { v0 += bias[col]; v1 += bias[col + 1]; }
                            *(float2*)(C + (size_t)r * ldc + col) = make_float2(v0, v1);
                        }
                    }
                }
            }
        }
        __syncthreads();
    }
}

// ---------------- finals: C += A[:,0:100]@B0 + A[:,100:200]@B1, Ncol=100 ----
__global__ void __launch_bounds__(256) gemm_fin_k(
    const float* __restrict__ A,
    const float* __restrict__ B,
    float* __restrict__ C)
{
    extern __shared__ uint32_t sm[];
    uint32_t* As = sm;               // [TBM][AST]
    uint32_t* Bs = sm + TBM * AST;   // [104][BST]

    const int t    = threadIdx.x;
    const int lane = t & 31;
    const int wid  = t >> 5;
    const int m0   = blockIdx.x * TBM;
    const int wm   = (wid >> 1) * 32;
    const int wn   = (wid & 1) * 32;

    for (int i = t; i < TBM * 8; i += 256) {
        int r = i >> 3;
        As[r * AST + 100 + (i & 7)] = 0;
    }
    for (int i = t; i < 4 * BST; i += 256)
        Bs[(100 + i / BST) * BST + (i % BST)] = 0;

    const int arow = wm + (lane >> 2);
    const int acol = lane & 3;
    const int brow = lane & 3;
    const int bcol = wn + (lane >> 2);

    for (int cidx = 0; cidx < 2; cidx++) {
        const int n0 = cidx * TBN;

        float acc[2][4][4];
#pragma unroll
        for (int mt = 0; mt < 2; mt++)
#pragma unroll
            for (int nt = 0; nt < 4; nt++)
#pragma unroll
                for (int r = 0; r < 4; r++) acc[mt][nt][r] = 0.f;

        for (int kh = 0; kh < 2; kh++) {
            __syncthreads();
            const float* Ap = A + kh * 100;
            const float* Bp = B + (size_t)(kh * 100) * HC;
            for (int i = t; i < TBM * 100; i += 256) {
                int r = i / 100, c = i - r * 100;
                int gr = m0 + r;
                float v = (gr < NN) ? Ap[(size_t)gr * 400 + c] : 0.f;
                As[r * AST + c] = f2tf32(v);
            }
            for (int i = t; i < 100 * TBN; i += 256) {
                int k = i >> 6, n = i & 63;
                int gc = n0 + n;
                Bs[k * BST + n] = f2tf32((gc < CC) ? Bp[(size_t)k * HC + gc] : 0.f);
            }
            __syncthreads();

#pragma unroll
            for (int ks = 0; ks < 13; ks++) {
                const int k0 = ks * 8;
                uint32_t a[2][4];
#pragma unroll
                for (int mt = 0; mt < 2; mt++) {
                    int r = arow + mt * 16;
                    a[mt][0] = As[r * AST + k0 + acol];
                    a[mt][1] = As[(r + 8) * AST + k0 + acol];
                    a[mt][2] = As[r * AST + k0 + acol + 4];
                    a[mt][3] = As[(r + 8) * AST + k0 + acol + 4];
                }
                uint32_t b[4][2];
#pragma unroll
                for (int nt = 0; nt < 4; nt++) {
                    b[nt][0] = Bs[(k0 + brow) * BST + bcol + nt * 8];
                    b[nt][1] = Bs[(k0 + brow + 4) * BST + bcol + nt * 8];
                }
#pragma unroll
                for (int mt = 0; mt < 2; mt++)
#pragma unroll
                    for (int nt = 0; nt < 4; nt++)
                        mma_tf32(acc[mt][nt], a[mt][0], a[mt][1], a[mt][2], a[mt][3],
                                 b[nt][0], b[nt][1]);
            }
        }

#pragma unroll
        for (int mt = 0; mt < 2; mt++) {
            int rbase = m0 + wm + mt * 16 + (lane >> 2);
#pragma unroll
            for (int half = 0; half < 2; half++) {
                int r = rbase + half * 8;
                if (r < NN) {
#pragma unroll
                    for (int nt = 0; nt < 4; nt++) {
                        int col = n0 + wn + nt * 8 + (lane & 3) * 2;
                        if (col < CC) {
                            float* cp = C + (size_t)r * HC + col;
                            float v0 = acc[mt][nt][half * 2 + 0] + cp[0];
                            float v1 = acc[mt][nt][half * 2 + 1] + cp[1];
                            *(float2*)cp = make_float2(v0, v1);
                        }
                    }
                }
            }
        }
    }
}

// ---------------- CSR build ----------------
__global__ void zero_cnt_k() {
    int i = blockIdx.x * blockDim.x + threadIdx.x;
    if (i < NN) d_cnt[i] = 0;
}
__global__ void hist_k(const int* __restrict__ ei) {
    int e = blockIdx.x * blockDim.x + threadIdx.x;
    if (e < EE) atomicAdd(&d_cnt[ei[EE + e]], 1);
}
__global__ void scan1_k() {
    __shared__ int ws[32];
    int i = blockIdx.x * 1024 + threadIdx.x;
    int v = (i < NN) ? d_cnt[i] : 0;
    int lane = threadIdx.x & 31, wid = threadIdx.x >> 5;
    int s = v;
#pragma unroll
    for (int d = 1; d < 32; d <<= 1) {
        int tv = __shfl_up_sync(0xffffffffu, s, d);
        if (lane >= d) s += tv;
    }
    if (lane == 31) ws[wid] = s;
    __syncthreads();
    if (wid == 0) {
        int t2 = ws[lane];
#pragma unroll
        for (int d = 1; d < 32; d <<= 1) {
            int tv = __shfl_up_sync(0xffffffffu, t2, d);
            if (lane >= d) t2 += tv;
        }
        ws[lane] = t2;
    }
    __syncthreads();
    int add = (wid > 0) ? ws[wid - 1] : 0;
    s += add;
    if (i < NN) d_tmpscan[i] = s;
    if (threadIdx.x == 1023) d_bsum[blockIdx.x] = s;
}
// parallel exclusive scan of block sums (nb <= 128)
__global__ void scan2_k(int nb) {
    __shared__ int sh[128];
    int t = threadIdx.x;
    int v = (t < nb) ? d_bsum[t] : 0;
    sh[t] = v;
    __syncthreads();
#pragma unroll
    for (int o = 1; o < 128; o <<= 1) {
        int u = (t >= o) ? sh[t - o] : 0;
        __syncthreads();
        sh[t] += u;
        __syncthreads();
    }
    if (t < nb) d_boff[t] = sh[t] - v;   // exclusive prefix
}
__global__ void scan3_k() {
    int i = blockIdx.x * blockDim.x + threadIdx.x;
    if (i < NN) {
        int rp = (i == 0) ? 0 : (d_tmpscan[i - 1] + d_boff[(i - 1) >> 10]);
        d_rowptr[i] = rp;
        d_cursor[i] = rp;
        if (i == NN - 1) d_rowptr[NN] = d_tmpscan[i] + d_boff[i >> 10];
    }
}
// scatter + precompute per-edge record {src, eid, rel}
__global__ void scatter_k(const int* __restrict__ ei,
                          const float* __restrict__ tarr,
                          const float* __restrict__ lastup) {
    int e = blockIdx.x * blockDim.x + threadIdx.x;
    if (e < EE) {
        int src = ei[e];
        int dst = ei[EE + e];
        float rel = fabsf(__ldg(lastup + src) - __ldg(tarr + e));
        int p = atomicAdd(&d_cursor[dst], 1);
        d_edge[p] = make_int4(src, e, __float_as_int(rel), 0);
    }
}

// ---------------- fused single-pass attention (no-max softmax) ----------------
__global__ void __launch_bounds__(128) attn_k(
    const float* __restrict__ msg,
    const float* __restrict__ w_time,
    const float* __restrict__ b_time,
    float* __restrict__ out)
{
    __shared__ float s_wt[TD], s_bt[TD];
    for (int i = threadIdx.x; i < TD; i += 128) { s_wt[i] = w_time[i]; s_bt[i] = b_time[i]; }
    __syncthreads();

    int warp = (blockIdx.x * 128 + threadIdx.x) >> 5;
    int lane = threadIdx.x & 31;
    if (warp >= NN) return;
    const int n = warp;
    const int base = d_rowptr[n];
    const int deg  = d_rowptr[n + 1] - base;

    const float2* frow2 = (const float2*)(d_fused + (size_t)n * FW);

    bool jok[4], jh1[4];
    int  ji[4];
#pragma unroll
    for (int s = 0; s < 4; s++) {
        int j2 = s * 64 + lane * 2;
        jok[s] = j2 < 200; jh1[s] = j2 >= 100; ji[s] = s * 32 + lane;
    }
    bool iok[2]; int ii[2]; int i2v[2];
#pragma unroll
    for (int r = 0; r < 2; r++) {
        int i2 = r * 64 + lane * 2;
        iok[r] = i2 < 100; ii[r] = r * 32 + lane; i2v[r] = i2;
    }

    const float2 zz = make_float2(0.f, 0.f);
    float2 qv[4];
#pragma unroll
    for (int s = 0; s < 4; s++) qv[s] = jok[s] ? frow2[ji[s]] : zz;
    float2 u0t[2], u0m[2], u1t[2], u1m[2];
#pragma unroll
    for (int r = 0; r < 2; r++) {
        u0t[r] = iok[r] ? frow2[400 + ii[r]] : zz;
        u0m[r] = iok[r] ? frow2[450 + ii[r]] : zz;
        u1t[r] = iok[r] ? frow2[500 + ii[r]] : zz;
        u1m[r] = iok[r] ? frow2[550 + ii[r]] : zz;
    }

    float den0 = 0.f, den1 = 0.f;
    float2 vac[4];
#pragma unroll
    for (int s = 0; s < 4; s++) vac[s] = zz;
    float2 e0t[2], e0m[2], e1t[2], e1m[2];
#pragma unroll
    for (int r = 0; r < 2; r++) { e0t[r] = zz; e0m[r] = zz; e1t[r] = zz; e1m[r] = zz; }

    float relA = 0.f, relB = 0.f;
    float2 kvA[4], vvA[4], mgA[2], kvB[4], vvB[4], mgB[2];

    auto load_edge = [&](int idx, float& rel, float2* kv, float2* vv, float2* mg) {
        int4 rec = d_edge[base + idx];          // {src, eid, rel_bits, 0}
        int src = rec.x, eid = rec.y;
        rel = __int_as_float(rec.z);
        const float2* s2 = (const float2*)(d_fused + (size_t)src * FW);
#pragma unroll
        for (int s = 0; s < 4; s++) {
            kv[s] = jok[s] ? s2[100 + ji[s]] : zz;
            vv[s] = jok[s] ? s2[200 + ji[s]] : zz;
        }
        const float2* m2 = (const float2*)(msg + (size_t)eid * 100);
#pragma unroll
        for (int r = 0; r < 2; r++) mg[r] = iok[r] ? m2[ii[r]] : zz;
    };

    auto process = [&](float rel, const float2* kv, const float2* vv, const float2* mg) {
        float2 te[2];
        float a0 = 0.f, a1 = 0.f;
#pragma unroll
        for (int r = 0; r < 2; r++) {
            if (iok[r]) {
                int i2 = i2v[r];
                float y0 = __fadd_rn(__fmul_rn(rel, s_wt[i2]),     s_bt[i2]);
                float y1 = __fadd_rn(__fmul_rn(rel, s_wt[i2 + 1]), s_bt[i2 + 1]);
                te[r].x = cos_acc(y0);
                te[r].y = cos_acc(y1);
            } else te[r] = zz;
            a0 += te[r].x * u0t[r].x + te[r].y * u0t[r].y
                + mg[r].x * u0m[r].x + mg[r].y * u0m[r].y;
            a1 += te[r].x * u1t[r].x + te[r].y * u1t[r].y
                + mg[r].x * u1m[r].x + mg[r].y * u1m[r].y;
        }
#pragma unroll
        for (int s = 0; s < 4; s++) {
            float dp = qv[s].x * kv[s].x + qv[s].y * kv[s].y;
            if (jh1[s]) a1 += dp; else a0 += dp;
        }
#pragma unroll
        for (int o = 16; o > 0; o >>= 1) {
            a0 += __shfl_xor_sync(0xffffffffu, a0, o);
            a1 += __shfl_xor_sync(0xffffffffu, a1, o);
        }

        float w0 = __expf(a0 * 0.1f);
        float w1 = __expf(a1 * 0.1f);
        den0 += w0;
        den1 += w1;
#pragma unroll
        for (int s = 0; s < 4; s++) {
            float w = jh1[s] ? w1 : w0;
            vac[s].x += w * vv[s].x;
            vac[s].y += w * vv[s].y;
        }
#pragma unroll
        for (int r = 0; r < 2; r++) {
            e0t[r].x += w0 * te[r].x;  e0t[r].y += w0 * te[r].y;
            e0m[r].x += w0 * mg[r].x;  e0m[r].y += w0 * mg[r].y;
            e1t[r].x += w1 * te[r].x;  e1t[r].y += w1 * te[r].y;
            e1m[r].x += w1 * mg[r].x;  e1m[r].y += w1 * mg[r].y;
        }
    };

    if (deg > 0) load_edge(0, relA, kvA, vvA, mgA);
    int d = 0;
    while (d < deg) {
        if (d + 1 < deg) load_edge(d + 1, relB, kvB, vvB, mgB);
        process(relA, kvA, vvA, mgA);
        if (++d >= deg) break;
        if (d + 1 < deg) load_edge(d + 1, relA, kvA, vvA, mgA);
        process(relB, kvB, vvB, mgB);
        ++d;
    }

    float inv0 = 1.f / (den0 + 1e-16f), inv1 = 1.f / (den1 + 1e-16f);
    float2* out2 = (float2*)(out + (size_t)n * HC);
#pragma unroll
    for (int s = 0; s < 4; s++) {
        if (jok[s]) {
            float inv = jh1[s] ? inv1 : inv0;
            float2 sk = frow2[300 + ji[s]];
            out2[ji[s]] = make_float2(sk.x + vac[s].x * inv, sk.y + vac[s].y * inv);
        }
    }
    float2* ae2 = (float2*)(d_aggea + (size_t)n * 400);
#pragma unroll
    for (int r = 0; r < 2; r++) {
        if (iok[r]) {
            ae2[ii[r]]       = make_float2(e0t[r].x * inv0, e0t[r].y * inv0);
            ae2[50 + ii[r]]  = make_float2(e0m[r].x * inv0, e0m[r].y * inv0);
            ae2[100 + ii[r]] = make_float2(e1t[r].x * inv1, e1t[r].y * inv1);
            ae2[150 + ii[r]] = make_float2(e1m[r].x * inv1, e1m[r].y * inv1);
        }
    }
}

// ---------------- launch (fork-join: CSR build overlaps mega GEMM) ----------
extern "C" void kernel_launch(void* const* d_in, const int* in_sizes, int n_in,
                              void* d_out, int out_size)
{
    const float* x       = (const float*)d_in[0];
    const float* last_up = (const float*)d_in[1];
    const int*   ei      = (const int*)  d_in[2];
    const float* tarr    = (const float*)d_in[3];
    const float* msg     = (const float*)d_in[4];
    const float* w_time  = (const float*)d_in[5];
    const float* b_time  = (const float*)d_in[6];
    const float* Wq      = (const float*)d_in[7];
    const float* bq      = (const float*)d_in[8];
    const float* Wk      = (const float*)d_in[9];
    const float* bk      = (const float*)d_in[10];
    const float* Wv      = (const float*)d_in[11];
    const float* bv      = (const float*)d_in[12];
    const float* We      = (const float*)d_in[13];
    const float* Ws      = (const float*)d_in[14];
    const float* bs      = (const float*)d_in[15];
    float* out = (float*)d_out;

    float *fused_p, *ae_p, *w_p, *b_p;
    cudaGetSymbolAddress((void**)&fused_p, d_fused);
    cudaGetSymbolAddress((void**)&ae_p,    d_aggea);
    cudaGetSymbolAddress((void**)&w_p,     d_W);
    cudaGetSymbolAddress((void**)&b_p,     d_bias);

    cudaFuncSetAttribute(gemm_tf32_k,
                         cudaFuncAttributeMaxDynamicSharedMemorySize, GEMM_SMEM);
    cudaFuncSetAttribute(gemm_fin_k,
                         cudaFuncAttributeMaxDynamicSharedMemorySize, GEMM_SMEM);

    // lazily created side stream + fork/join events (first call is the
    // uncaptured correctness run; no device memory is allocated)
    static cudaStream_t s2 = nullptr;
    static cudaEvent_t evA = nullptr, evB = nullptr;
    if (!s2) {
        cudaStreamCreateWithFlags(&s2, cudaStreamNonBlocking);
        cudaEventCreateWithFlags(&evA, cudaEventDisableTiming);
        cudaEventCreateWithFlags(&evB, cudaEventDisableTiming);
    }

    // fork: side stream joins capture
    cudaEventRecord(evA, 0);
    cudaStreamWaitEvent(s2, evA, 0);

    pack_w_k<<<(100 * FW + 255) / 256, 256>>>(Wq, Wk, Wv, Ws, We);   // 0 (main)
    pack_b_k<<<(FW + 255) / 256, 256>>>(bq, bk, bv, bs, We);         // 1 (main)
    zero_cnt_k<<<(NN + 255) / 256, 256, 0, s2>>>();                  // 2 (side)

    const int gx = (NN + TBM - 1) / TBM;   // 782
    // 3 (profiled slot, main): mega GEMM — runs concurrent with CSR chain
    gemm_tf32_k<<<gx, 256, GEMM_SMEM>>>(x, 100, w_p, FW, fused_p, FW,
                                        NN, FW, b_p);

    // CSR chain continues on side stream
    hist_k<<<(EE + 255) / 256, 256, 0, s2>>>(ei);
    int nb = (NN + 1023) / 1024;
    scan1_k<<<nb, 1024, 0, s2>>>();
    scan2_k<<<1, 128, 0, s2>>>(nb);
    scan3_k<<<(NN + 255) / 256, 256, 0, s2>>>();
    scatter_k<<<(EE + 255) / 256, 256, 0, s2>>>(ei, tarr, last_up);
    cudaEventRecord(evB, s2);

    // join: attention needs both the mega GEMM (main) and CSR (side)
    cudaStreamWaitEvent(0, evB, 0);
    attn_k<<<(NN + 3) / 4, 128>>>(msg, w_time, b_time, out);

    // finals: one fused K=200 accumulate per head
    for (int h = 0; h < 2; h++) {
        gemm_fin_k<<<gx, 256, GEMM_SMEM>>>(ae_p + h * 200, We + h * 100,
                                           out + h * 100);
    }
}

// round 14
// speedup vs baseline: 1.0975x; 1.0124x over previous
#include <cuda_runtime.h>
#include <math.h>
#include <stdint.h>

#define NN 100000
#define EE 400000
#define HC 200      // HEADS*OUT_CH
#define CC 100      // OUT_CH
#define TD 100      // TIME_DIM
#define FW 1200     // fused width: q(200)|k(200)|v(200)|skip(200)|u(400)
#define TBM 128
#define TBN 64
#define BST 72
#define AST 108
#define GEMM_SMEM ((TBM * AST + 104 * BST) * 4)

// ---------------- scratch (device globals; allocation-free) ----------------
__device__ __align__(16) float d_fused[(size_t)NN * FW];   // 480 MB
__device__ __align__(16) float d_aggea[(size_t)NN * 400];  // 160 MB
__device__ __align__(16) float d_W[100 * FW];
__device__ __align__(16) float d_bias[FW];
__device__ __align__(16) int4  d_edge[EE];                 // {src, eid, rel_bits, 0}
__device__ int d_cnt[NN];
__device__ int d_rowptr[NN + 1];
__device__ int d_cursor[NN];
__device__ int d_tmpscan[NN];
__device__ int d_bsum[256];
__device__ int d_boff[256];

// ---------------- accurate cos: fp32 Cody-Waite reduction + MUFU cos ------
// After reduction |r| <= pi, where __cosf max abs error is ~2^-21.2 (4.3e-7),
// far below the tf32 error floor of ~3.4e-4.
__device__ __forceinline__ float cos_acc(float y) {
    float k = rintf(y * 0.15915494309189535f);
    float r = fmaf(k, -6.2831854820251465f, y);
    r = fmaf(k, 1.7484556000744e-7f, r);
    return __cosf(r);
}

__device__ __forceinline__ uint32_t f2tf32(float f) {
    uint32_t u;
    asm("cvt.rna.tf32.f32 %0, %1;" : "=r"(u) : "f"(f));
    return u;
}

__device__ __forceinline__ void mma_tf32(float c[4],
                                         uint32_t a0, uint32_t a1, uint32_t a2, uint32_t a3,
                                         uint32_t b0, uint32_t b1) {
    asm volatile(
        "mma.sync.aligned.m16n8k8.row.col.f32.tf32.tf32.f32 "
        "{%0,%1,%2,%3}, {%4,%5,%6,%7}, {%8,%9}, {%0,%1,%2,%3};"
        : "+f"(c[0]), "+f"(c[1]), "+f"(c[2]), "+f"(c[3])
        : "r"(a0), "r"(a1), "r"(a2), "r"(a3), "r"(b0), "r"(b1));
}

// ---------------- weight packing ----------------
__global__ void pack_w_k(const float* __restrict__ Wq, const float* __restrict__ Wk,
                         const float* __restrict__ Wv, const float* __restrict__ Ws,
                         const float* __restrict__ We) {
    int idx = blockIdx.x * blockDim.x + threadIdx.x;
    if (idx >= 100 * FW) return;
    int k = idx / FW;
    int c = idx % FW;
    float val;
    if (c < 200)       val = Wq[k * HC + c];
    else if (c < 400)  val = Wk[k * HC + (c - 200)];
    else if (c < 600)  val = Wv[k * HC + (c - 400)];
    else if (c < 800)  val = Ws[k * HC + (c - 600)];
    else {
        int c2 = c - 800;
        int h = c2 / 200, i = c2 % 200;
        float s = 0.f;
        for (int cc = 0; cc < CC; cc++)
            s += Wq[k * HC + h * CC + cc] * We[i * HC + h * CC + cc];
        val = s;
    }
    d_W[idx] = val;
}

__global__ void pack_b_k(const float* __restrict__ bq, const float* __restrict__ bk,
                         const float* __restrict__ bv, const float* __restrict__ bs,
                         const float* __restrict__ We) {
    int c = blockIdx.x * blockDim.x + threadIdx.x;
    if (c >= FW) return;
    float val;
    if (c < 200)       val = bq[c];
    else if (c < 400)  val = bk[c - 200];
    else if (c < 600)  val = bv[c - 400];
    else if (c < 800)  val = bs[c - 600];
    else {
        int c2 = c - 800;
        int h = c2 / 200, i = c2 % 200;
        float s = 0.f;
        for (int cc = 0; cc < CC; cc++)
            s += bq[h * CC + cc] * We[i * HC + h * CC + cc];
        val = s;
    }
    d_bias[c] = val;
}

// ---------------- tf32 tensor-core GEMM (K=100, A resident) ----------------
__global__ void __launch_bounds__(256) gemm_tf32_k(
    const float* __restrict__ A, int lda,
    const float* __restrict__ B, int ldb,
    float* __restrict__ C, int ldc,
    int M, int Ncol,
    const float* __restrict__ bias)
{
    extern __shared__ uint32_t sm[];
    uint32_t* As = sm;               // [TBM][AST]
    uint32_t* Bs = sm + TBM * AST;   // [104][BST]

    const int t    = threadIdx.x;
    const int lane = t & 31;
    const int wid  = t >> 5;
    const int m0   = blockIdx.x * TBM;
    const int wm   = (wid >> 1) * 32;
    const int wn   = (wid & 1) * 32;

    for (int i = t; i < TBM * 8; i += 256) {
        int r = i >> 3;
        As[r * AST + 100 + (i & 7)] = 0;
    }
    for (int i = t; i < 4 * BST; i += 256)
        Bs[(100 + i / BST) * BST + (i % BST)] = 0;

    for (int i = t; i < TBM * 100; i += 256) {
        int r = i / 100, c = i - r * 100;
        int gr = m0 + r;
        float v = (gr < M) ? A[(size_t)gr * lda + c] : 0.f;
        As[r * AST + c] = f2tf32(v);
    }

    const int nch = (Ncol + TBN - 1) / TBN;
    float pb[25];
#pragma unroll
    for (int j = 0; j < 25; j++) {
        int i = t + j * 256;
        int k = i >> 6, n = i & 63;
        pb[j] = (n < Ncol) ? B[(size_t)k * ldb + n] : 0.f;
    }
    __syncthreads();

    const int arow = wm + (lane >> 2);
    const int acol = lane & 3;
    const int brow = lane & 3;
    const int bcol = wn + (lane >> 2);

    for (int cidx = 0; cidx < nch; cidx++) {
#pragma unroll
        for (int j = 0; j < 25; j++) {
            int i = t + j * 256;
            int k = i >> 6, n = i & 63;
            Bs[k * BST + n] = f2tf32(pb[j]);
        }
        __syncthreads();

        const int n0 = cidx * TBN;
        if (cidx + 1 < nch) {
            int n0n = n0 + TBN;
#pragma unroll
            for (int j = 0; j < 25; j++) {
                int i = t + j * 256;
                int k = i >> 6, n = i & 63;
                int gc = n0n + n;
                pb[j] = (gc < Ncol) ? B[(size_t)k * ldb + gc] : 0.f;
            }
        }

        float acc[2][4][4];
#pragma unroll
        for (int mt = 0; mt < 2; mt++)
#pragma unroll
            for (int nt = 0; nt < 4; nt++)
#pragma unroll
                for (int r = 0; r < 4; r++) acc[mt][nt][r] = 0.f;

#pragma unroll
        for (int ks = 0; ks < 13; ks++) {
            const int k0 = ks * 8;
            uint32_t a[2][4];
#pragma unroll
            for (int mt = 0; mt < 2; mt++) {
                int r = arow + mt * 16;
                a[mt][0] = As[r * AST + k0 + acol];
                a[mt][1] = As[(r + 8) * AST + k0 + acol];
                a[mt][2] = As[r * AST + k0 + acol + 4];
                a[mt][3] = As[(r + 8) * AST + k0 + acol + 4];
            }
            uint32_t b[4][2];
#pragma unroll
            for (int nt = 0; nt < 4; nt++) {
                b[nt][0] = Bs[(k0 + brow) * BST + bcol + nt * 8];
                b[nt][1] = Bs[(k0 + brow + 4) * BST + bcol + nt * 8];
            }
#pragma unroll
            for (int mt = 0; mt < 2; mt++)
#pragma unroll
                for (int nt = 0; nt < 4; nt++)
                    mma_tf32(acc[mt][nt], a[mt][0], a[mt][1], a[mt][2], a[mt][3],
                             b[nt][0], b[nt][1]);
        }

#pragma unroll
        for (int mt = 0; mt < 2; mt++) {
            int rbase = m0 + wm + mt * 16 + (lane >> 2);
#pragma unroll
            for (int half = 0; half < 2; half++) {
                int r = rbase + half * 8;
                if (r < M) {
#pragma unroll
                    for (int nt = 0; nt < 4; nt++) {
                        int col = n0 + wn + nt * 8 + (lane & 3) * 2;
                        if (col < Ncol) {
                            float v0 = acc[mt][nt][half * 2 + 0];
                            float v1 = acc[mt][nt][half * 2 + 1];
                            if (bias) { v0 += bias[col]; v1 += bias[col + 1]; }
                            *(float2*)(C + (size_t)r * ldc + col) = make_float2(v0, v1);
                        }
                    }
                }
            }
        }
        __syncthreads();
    }
}

// ---------------- finals: C += A[:,0:100]@B0 + A[:,100:200]@B1, Ncol=100 ----
__global__ void __launch_bounds__(256) gemm_fin_k(
    const float* __restrict__ A,
    const float* __restrict__ B,
    float* __restrict__ C)
{
    extern __shared__ uint32_t sm[];
    uint32_t* As = sm;               // [TBM][AST]
    uint32_t* Bs = sm + TBM * AST;   // [104][BST]

    const int t    = threadIdx.x;
    const int lane = t & 31;
    const int wid  = t >> 5;
    const int m0   = blockIdx.x * TBM;
    const int wm   = (wid >> 1) * 32;
    const int wn   = (wid & 1) * 32;

    for (int i = t; i < TBM * 8; i += 256) {
        int r = i >> 3;
        As[r * AST + 100 + (i & 7)] = 0;
    }
    for (int i = t; i < 4 * BST; i += 256)
        Bs[(100 + i / BST) * BST + (i % BST)] = 0;

    const int arow = wm + (lane >> 2);
    const int acol = lane & 3;
    const int brow = lane & 3;
    const int bcol = wn + (lane >> 2);

    for (int cidx = 0; cidx < 2; cidx++) {
        const int n0 = cidx * TBN;

        float acc[2][4][4];
#pragma unroll
        for (int mt = 0; mt < 2; mt++)
#pragma unroll
            for (int nt = 0; nt < 4; nt++)
#pragma unroll
                for (int r = 0; r < 4; r++) acc[mt][nt][r] = 0.f;

        for (int kh = 0; kh < 2; kh++) {
            __syncthreads();
            const float* Ap = A + kh * 100;
            const float* Bp = B + (size_t)(kh * 100) * HC;
            for (int i = t; i < TBM * 100; i += 256) {
                int r = i / 100, c = i - r * 100;
                int gr = m0 + r;
                float v = (gr < NN) ? Ap[(size_t)gr * 400 + c] : 0.f;
                As[r * AST + c] = f2tf32(v);
            }
            for (int i = t; i < 100 * TBN; i += 256) {
                int k = i >> 6, n = i & 63;
                int gc = n0 + n;
                Bs[k * BST + n] = f2tf32((gc < CC) ? Bp[(size_t)k * HC + gc] : 0.f);
            }
            __syncthreads();

#pragma unroll
            for (int ks = 0; ks < 13; ks++) {
                const int k0 = ks * 8;
                uint32_t a[2][4];
#pragma unroll
                for (int mt = 0; mt < 2; mt++) {
                    int r = arow + mt * 16;
                    a[mt][0] = As[r * AST + k0 + acol];
                    a[mt][1] = As[(r + 8) * AST + k0 + acol];
                    a[mt][2] = As[r * AST + k0 + acol + 4];
                    a[mt][3] = As[(r + 8) * AST + k0 + acol + 4];
                }
                uint32_t b[4][2];
#pragma unroll
                for (int nt = 0; nt < 4; nt++) {
                    b[nt][0] = Bs[(k0 + brow) * BST + bcol + nt * 8];
                    b[nt][1] = Bs[(k0 + brow + 4) * BST + bcol + nt * 8];
                }
#pragma unroll
                for (int mt = 0; mt < 2; mt++)
#pragma unroll
                    for (int nt = 0; nt < 4; nt++)
                        mma_tf32(acc[mt][nt], a[mt][0], a[mt][1], a[mt][2], a[mt][3],
                                 b[nt][0], b[nt][1]);
            }
        }

#pragma unroll
        for (int mt = 0; mt < 2; mt++) {
            int rbase = m0 + wm + mt * 16 + (lane >> 2);
#pragma unroll
            for (int half = 0; half < 2; half++) {
                int r = rbase + half * 8;
                if (r < NN) {
#pragma unroll
                    for (int nt = 0; nt < 4; nt++) {
                        int col = n0 + wn + nt * 8 + (lane & 3) * 2;
                        if (col < CC) {
                            float* cp = C + (size_t)r * HC + col;
                            float v0 = acc[mt][nt][half * 2 + 0] + cp[0];
                            float v1 = acc[mt][nt][half * 2 + 1] + cp[1];
                            *(float2*)cp = make_float2(v0, v1);
                        }
                    }
                }
            }
        }
    }
}

// ---------------- CSR build ----------------
__global__ void zero_cnt_k() {
    int i = blockIdx.x * blockDim.x + threadIdx.x;
    if (i < NN) d_cnt[i] = 0;
}
__global__ void hist_k(const int* __restrict__ ei) {
    int e = blockIdx.x * blockDim.x + threadIdx.x;
    if (e < EE) atomicAdd(&d_cnt[ei[EE + e]], 1);
}
__global__ void scan1_k() {
    __shared__ int ws[32];
    int i = blockIdx.x * 1024 + threadIdx.x;
    int v = (i < NN) ? d_cnt[i] : 0;
    int lane = threadIdx.x & 31, wid = threadIdx.x >> 5;
    int s = v;
#pragma unroll
    for (int d = 1; d < 32; d <<= 1) {
        int tv = __shfl_up_sync(0xffffffffu, s, d);
        if (lane >= d) s += tv;
    }
    if (lane == 31) ws[wid] = s;
    __syncthreads();
    if (wid == 0) {
        int t2 = ws[lane];
#pragma unroll
        for (int d = 1; d < 32; d <<= 1) {
            int tv = __shfl_up_sync(0xffffffffu, t2, d);
            if (lane >= d) t2 += tv;
        }
        ws[lane] = t2;
    }
    __syncthreads();
    int add = (wid > 0) ? ws[wid - 1] : 0;
    s += add;
    if (i < NN) d_tmpscan[i] = s;
    if (threadIdx.x == 1023) d_bsum[blockIdx.x] = s;
}
// parallel exclusive scan of block sums (nb <= 128)
__global__ void scan2_k(int nb) {
    __shared__ int sh[128];
    int t = threadIdx.x;
    int v = (t < nb) ? d_bsum[t] : 0;
    sh[t] = v;
    __syncthreads();
#pragma unroll
    for (int o = 1; o < 128; o <<= 1) {
        int u = (t >= o) ? sh[t - o] : 0;
        __syncthreads();
        sh[t] += u;
        __syncthreads();
    }
    if (t < nb) d_boff[t] = sh[t] - v;   // exclusive prefix
}
__global__ void scan3_k() {
    int i = blockIdx.x * blockDim.x + threadIdx.x;
    if (i < NN) {
        int rp = (i == 0) ? 0 : (d_tmpscan[i - 1] + d_boff[(i - 1) >> 10]);
        d_rowptr[i] = rp;
        d_cursor[i] = rp;
        if (i == NN - 1) d_rowptr[NN] = d_tmpscan[i] + d_boff[i >> 10];
    }
}
// scatter + precompute per-edge record {src, eid, rel}
__global__ void scatter_k(const int* __restrict__ ei,
                          const float* __restrict__ tarr,
                          const float* __restrict__ lastup) {
    int e = blockIdx.x * blockDim.x + threadIdx.x;
    if (e < EE) {
        int src = ei[e];
        int dst = ei[EE + e];
        float rel = fabsf(__ldg(lastup + src) - __ldg(tarr + e));
        int p = atomicAdd(&d_cursor[dst], 1);
        d_edge[p] = make_int4(src, e, __float_as_int(rel), 0);
    }
}

// ---------------- fused single-pass attention (no-max softmax) ----------------
__global__ void __launch_bounds__(128) attn_k(
    const float* __restrict__ msg,
    const float* __restrict__ w_time,
    const float* __restrict__ b_time,
    float* __restrict__ out)
{
    __shared__ float s_wt[TD], s_bt[TD];
    for (int i = threadIdx.x; i < TD; i += 128) { s_wt[i] = w_time[i]; s_bt[i] = b_time[i]; }
    __syncthreads();

    int warp = (blockIdx.x * 128 + threadIdx.x) >> 5;
    int lane = threadIdx.x & 31;
    if (warp >= NN) return;
    const int n = warp;
    const int base = d_rowptr[n];
    const int deg  = d_rowptr[n + 1] - base;

    const float2* frow2 = (const float2*)(d_fused + (size_t)n * FW);

    bool jok[4], jh1[4];
    int  ji[4];
#pragma unroll
    for (int s = 0; s < 4; s++) {
        int j2 = s * 64 + lane * 2;
        jok[s] = j2 < 200; jh1[s] = j2 >= 100; ji[s] = s * 32 + lane;
    }
    bool iok[2]; int ii[2]; int i2v[2];
#pragma unroll
    for (int r = 0; r < 2; r++) {
        int i2 = r * 64 + lane * 2;
        iok[r] = i2 < 100; ii[r] = r * 32 + lane; i2v[r] = i2;
    }

    const float2 zz = make_float2(0.f, 0.f);
    float2 qv[4];
#pragma unroll
    for (int s = 0; s < 4; s++) qv[s] = jok[s] ? frow2[ji[s]] : zz;
    float2 u0t[2], u0m[2], u1t[2], u1m[2];
#pragma unroll
    for (int r = 0; r < 2; r++) {
        u0t[r] = iok[r] ? frow2[400 + ii[r]] : zz;
        u0m[r] = iok[r] ? frow2[450 + ii[r]] : zz;
        u1t[r] = iok[r] ? frow2[500 + ii[r]] : zz;
        u1m[r] = iok[r] ? frow2[550 + ii[r]] : zz;
    }

    float den0 = 0.f, den1 = 0.f;
    float2 vac[4];
#pragma unroll
    for (int s = 0; s < 4; s++) vac[s] = zz;
    float2 e0t[2], e0m[2], e1t[2], e1m[2];
#pragma unroll
    for (int r = 0; r < 2; r++) { e0t[r] = zz; e0m[r] = zz; e1t[r] = zz; e1m[r] = zz; }

    float relA = 0.f, relB = 0.f;
    float2 kvA[4], vvA[4], mgA[2], kvB[4], vvB[4], mgB[2];

    auto load_edge = [&](int idx, float& rel, float2* kv, float2* vv, float2* mg) {
        int4 rec = d_edge[base + idx];          // {src, eid, rel_bits, 0}
        int src = rec.x, eid = rec.y;
        rel = __int_as_float(rec.z);
        const float2* s2 = (const float2*)(d_fused + (size_t)src * FW);
#pragma unroll
        for (int s = 0; s < 4; s++) {
            kv[s] = jok[s] ? s2[100 + ji[s]] : zz;
            vv[s] = jok[s] ? s2[200 + ji[s]] : zz;
        }
        const float2* m2 = (const float2*)(msg + (size_t)eid * 100);
#pragma unroll
        for (int r = 0; r < 2; r++) mg[r] = iok[r] ? m2[ii[r]] : zz;
    };

    auto process = [&](float rel, const float2* kv, const float2* vv, const float2* mg) {
        float2 te[2];
        float a0 = 0.f, a1 = 0.f;
#pragma unroll
        for (int r = 0; r < 2; r++) {
            if (iok[r]) {
                int i2 = i2v[r];
                float y0 = __fadd_rn(__fmul_rn(rel, s_wt[i2]),     s_bt[i2]);
                float y1 = __fadd_rn(__fmul_rn(rel, s_wt[i2 + 1]), s_bt[i2 + 1]);
                te[r].x = cos_acc(y0);
                te[r].y = cos_acc(y1);
            } else te[r] = zz;
            a0 += te[r].x * u0t[r].x + te[r].y * u0t[r].y
                + mg[r].x * u0m[r].x + mg[r].y * u0m[r].y;
            a1 += te[r].x * u1t[r].x + te[r].y * u1t[r].y
                + mg[r].x * u1m[r].x + mg[r].y * u1m[r].y;
        }
#pragma unroll
        for (int s = 0; s < 4; s++) {
            float dp = qv[s].x * kv[s].x + qv[s].y * kv[s].y;
            if (jh1[s]) a1 += dp; else a0 += dp;
        }
#pragma unroll
        for (int o = 16; o > 0; o >>= 1) {
            a0 += __shfl_xor_sync(0xffffffffu, a0, o);
            a1 += __shfl_xor_sync(0xffffffffu, a1, o);
        }

        float w0 = __expf(a0 * 0.1f);
        float w1 = __expf(a1 * 0.1f);
        den0 += w0;
        den1 += w1;
#pragma unroll
        for (int s = 0; s < 4; s++) {
            float w = jh1[s] ? w1 : w0;
            vac[s].x += w * vv[s].x;
            vac[s].y += w * vv[s].y;
        }
#pragma unroll
        for (int r = 0; r < 2; r++) {
            e0t[r].x += w0 * te[r].x;  e0t[r].y += w0 * te[r].y;
            e0m[r].x += w0 * mg[r].x;  e0m[r].y += w0 * mg[r].y;
            e1t[r].x += w1 * te[r].x;  e1t[r].y += w1 * te[r].y;
            e1m[r].x += w1 * mg[r].x;  e1m[r].y += w1 * mg[r].y;
        }
    };

    if (deg > 0) load_edge(0, relA, kvA, vvA, mgA);
    int d = 0;
    while (d < deg) {
        if (d + 1 < deg) load_edge(d + 1, relB, kvB, vvB, mgB);
        process(relA, kvA, vvA, mgA);
        if (++d >= deg) break;
        if (d + 1 < deg) load_edge(d + 1, relA, kvA, vvA, mgA);
        process(relB, kvB, vvB, mgB);
        ++d;
    }

    float inv0 = 1.f / (den0 + 1e-16f), inv1 = 1.f / (den1 + 1e-16f);
    float2* out2 = (float2*)(out + (size_t)n * HC);
#pragma unroll
    for (int s = 0; s < 4; s++) {
        if (jok[s]) {
            float inv = jh1[s] ? inv1 : inv0;
            float2 sk = frow2[300 + ji[s]];
            out2[ji[s]] = make_float2(sk.x + vac[s].x * inv, sk.y + vac[s].y * inv);
        }
    }
    float2* ae2 = (float2*)(d_aggea + (size_t)n * 400);
#pragma unroll
    for (int r = 0; r < 2; r++) {
        if (iok[r]) {
            ae2[ii[r]]       = make_float2(e0t[r].x * inv0, e0t[r].y * inv0);
            ae2[50 + ii[r]]  = make_float2(e0m[r].x * inv0, e0m[r].y * inv0);
            ae2[100 + ii[r]] = make_float2(e1t[r].x * inv1, e1t[r].y * inv1);
            ae2[150 + ii[r]] = make_float2(e1m[r].x * inv1, e1m[r].y * inv1);
        }
    }
}

// ---------------- launch (fork-join: CSR build overlaps mega GEMM) ----------
extern "C" void kernel_launch(void* const* d_in, const int* in_sizes, int n_in,
                              void* d_out, int out_size)
{
    const float* x       = (const float*)d_in[0];
    const float* last_up = (const float*)d_in[1];
    const int*   ei      = (const int*)  d_in[2];
    const float* tarr    = (const float*)d_in[3];
    const float* msg     = (const float*)d_in[4];
    const float* w_time  = (const float*)d_in[5];
    const float* b_time  = (const float*)d_in[6];
    const float* Wq      = (const float*)d_in[7];
    const float* bq      = (const float*)d_in[8];
    const float* Wk      = (const float*)d_in[9];
    const float* bk      = (const float*)d_in[10];
    const float* Wv      = (const float*)d_in[11];
    const float* bv      = (const float*)d_in[12];
    const float* We      = (const float*)d_in[13];
    const float* Ws      = (const float*)d_in[14];
    const float* bs      = (const float*)d_in[15];
    float* out = (float*)d_out;

    float *fused_p, *ae_p, *w_p, *b_p;
    cudaGetSymbolAddress((void**)&fused_p, d_fused);
    cudaGetSymbolAddress((void**)&ae_p,    d_aggea);
    cudaGetSymbolAddress((void**)&w_p,     d_W);
    cudaGetSymbolAddress((void**)&b_p,     d_bias);

    cudaFuncSetAttribute(gemm_tf32_k,
                         cudaFuncAttributeMaxDynamicSharedMemorySize, GEMM_SMEM);
    cudaFuncSetAttribute(gemm_fin_k,
                         cudaFuncAttributeMaxDynamicSharedMemorySize, GEMM_SMEM);

    static cudaStream_t s2 = nullptr;
    static cudaEvent_t evA = nullptr, evB = nullptr;
    if (!s2) {
        cudaStreamCreateWithFlags(&s2, cudaStreamNonBlocking);
        cudaEventCreateWithFlags(&evA, cudaEventDisableTiming);
        cudaEventCreateWithFlags(&evB, cudaEventDisableTiming);
    }

    // fork: side stream joins capture
    cudaEventRecord(evA, 0);
    cudaStreamWaitEvent(s2, evA, 0);

    pack_w_k<<<(100 * FW + 255) / 256, 256>>>(Wq, Wk, Wv, Ws, We);   // 0 (main)
    pack_b_k<<<(FW + 255) / 256, 256>>>(bq, bk, bv, bs, We);         // 1 (main)
    zero_cnt_k<<<(NN + 255) / 256, 256, 0, s2>>>();                  // 2 (side)

    const int gx = (NN + TBM - 1) / TBM;   // 782
    // 3 (profiled slot, main): mega GEMM — concurrent with CSR chain
    gemm_tf32_k<<<gx, 256, GEMM_SMEM>>>(x, 100, w_p, FW, fused_p, FW,
                                        NN, FW, b_p);

    hist_k<<<(EE + 255) / 256, 256, 0, s2>>>(ei);
    int nb = (NN + 1023) / 1024;
    scan1_k<<<nb, 1024, 0, s2>>>();
    scan2_k<<<1, 128, 0, s2>>>(nb);
    scan3_k<<<(NN + 255) / 256, 256, 0, s2>>>();
    scatter_k<<<(EE + 255) / 256, 256, 0, s2>>>(ei, tarr, last_up);
    cudaEventRecord(evB, s2);

    // join: attention needs both the mega GEMM (main) and CSR (side)
    cudaStreamWaitEvent(0, evB, 0);
    attn_k<<<(NN + 3) / 4, 128>>>(msg, w_time, b_time, out);

    // finals: one fused K=200 accumulate per head
    for (int h = 0; h < 2; h++) {
        gemm_fin_k<<<gx, 256, GEMM_SMEM>>>(ae_p + h * 200, We + h * 100,
                                           out + h * 100);
    }
}